// round 5
// baseline (speedup 1.0000x reference)
#include <cuda_runtime.h>
#include <cuda_bf16.h>
#include <math.h>
#include <stdint.h>

#define Hh 256
#define NMAX 262144
#define BMAX 4096

// ---------------- device scratch (no allocations allowed) ----------------
__device__ float d_e[NMAX];                  // fallback only
__device__ int   d_starts[BMAX + 1];
__device__ int   d_is64;
__device__ float d_q[BMAX * 256];            // q = h1 (fp32, for attention)
__device__ float d_gates[BMAX * 1024];
__device__ float d_c0[BMAX * 256];
__device__ float d_c1[BMAX * 256];
// bf16 split operands for GEMMs
__device__ __nv_bfloat16 d_X0h[BMAX * 768], d_X0l[BMAX * 768];   // [q_star(512)|h0(256)]
__device__ __nv_bfloat16 d_X1h[BMAX * 512], d_X1l[BMAX * 512];   // [h0(256)|h1(256)]
__device__ __nv_bfloat16 d_W0h[1024 * 768], d_W0l[1024 * 768];   // [Wih0|Whh0]
__device__ __nv_bfloat16 d_W1h[1024 * 512], d_W1l[1024 * 512];   // [Wih1|Whh1]
__device__ float d_b0[1024], d_b1[1024];

// ---------------- small helpers ----------------
__device__ __forceinline__ uint32_t smem_u32(const void* p) {
    uint32_t a;
    asm("{ .reg .u64 t; cvta.to.shared.u64 t, %1; cvt.u32.u64 %0, t; }" : "=r"(a) : "l"(p));
    return a;
}
__device__ __forceinline__ void cp16(uint32_t dst, const void* src) {
    asm volatile("cp.async.cg.shared.global [%0], [%1], 16;" :: "r"(dst), "l"(src));
}
#define CP_COMMIT() asm volatile("cp.async.commit_group;" ::: "memory")
#define CP_WAIT1()  asm volatile("cp.async.wait_group 1;" ::: "memory")
#define CP_WAIT0()  asm volatile("cp.async.wait_group 0;" ::: "memory")

__device__ __forceinline__ void ldsm4(uint32_t* r, uint32_t addr) {
    asm volatile("ldmatrix.sync.aligned.m8n8.x4.shared.b16 {%0,%1,%2,%3}, [%4];"
                 : "=r"(r[0]), "=r"(r[1]), "=r"(r[2]), "=r"(r[3]) : "r"(addr));
}
__device__ __forceinline__ void mma16816(float* c, const uint32_t* a, const uint32_t* b) {
    asm volatile(
        "mma.sync.aligned.m16n8k16.row.col.f32.bf16.bf16.f32 "
        "{%0,%1,%2,%3},{%4,%5,%6,%7},{%8,%9},{%0,%1,%2,%3};"
        : "+f"(c[0]), "+f"(c[1]), "+f"(c[2]), "+f"(c[3])
        : "r"(a[0]), "r"(a[1]), "r"(a[2]), "r"(a[3]), "r"(b[0]), "r"(b[1]));
}
__device__ __forceinline__ void split_bf16(float x, __nv_bfloat16& h, __nv_bfloat16& l) {
    h = __float2bfloat16(x);
    l = __float2bfloat16(x - __bfloat162float(h));
}

// ---------------- graph_id dtype detection ----------------
__global__ void detect_kernel(const int* p, int N) {
    int z = 1;
    for (int j = 0; j < 8; j++) {
        int idx = N - 1 - 2 * j;
        if (idx < 1) break;
        if ((idx & 1) == 0) idx--;
        if (idx >= 1 && p[idx] != 0) z = 0;
    }
    d_is64 = z;
}
__device__ __forceinline__ int get_gid(const void* p, int i) {
    if (d_is64) return (int)((const long long*)p)[i];
    return ((const int*)p)[i];
}
__global__ void starts_kernel(const void* gid, int N, int B) {
    int g = blockIdx.x * blockDim.x + threadIdx.x;
    if (g > B) return;
    int lo = 0, hi = N;
    while (lo < hi) {
        int mid = (lo + hi) >> 1;
        if (get_gid(gid, mid) < g) lo = mid + 1; else hi = mid;
    }
    d_starts[g] = lo;
}

// ---------------- pack weights (bf16 split) + summed biases ----------------
__global__ void pack_kernel(const float* __restrict__ Wih0, const float* __restrict__ Whh0,
                            const float* __restrict__ bih0, const float* __restrict__ bhh0,
                            const float* __restrict__ Wih1, const float* __restrict__ Whh1,
                            const float* __restrict__ bih1, const float* __restrict__ bhh1) {
    int i = blockIdx.x * blockDim.x + threadIdx.x;
    if (i < 1024 * 768) {
        int j = i / 768, k = i % 768;
        float v = (k < 512) ? Wih0[j * 512 + k] : Whh0[j * 256 + (k - 512)];
        split_bf16(v, d_W0h[i], d_W0l[i]);
    }
    if (i < 1024 * 512) {
        int j = i / 512, k = i % 512;
        float v = (k < 256) ? Wih1[j * 256 + k] : Whh1[j * 256 + (k - 256)];
        split_bf16(v, d_W1h[i], d_W1l[i]);
    }
    if (i < 1024) {
        d_b0[i] = bih0[i] + bhh0[i];
        d_b1[i] = bih1[i] + bhh1[i];
    }
}

// ---------------- zero-init state ----------------
__global__ void init_kernel(int B) {
    int i = blockIdx.x * blockDim.x + threadIdx.x;
    __nv_bfloat16 z = __float2bfloat16(0.f);
    if (i < B * 768) { d_X0h[i] = z; d_X0l[i] = z; }
    if (i < B * 512) { d_X1h[i] = z; d_X1l[i] = z; }
    if (i < B * 256) { d_c0[i] = 0.f; d_c1[i] = 0.f; d_q[i] = 0.f; }
}

// ---------------- attention: SMEM-cached single global pass ----------------
// One CTA (512 threads) per graph. Node rows cached in dynamic SMEM (cap 192
// rows); fallback streams from global for oversized segments (never expected).
#define CAP 192
#define ATT_SMEM ((CAP * 256 + CAP + 256 + 16 + 256) * 4)

__global__ __launch_bounds__(512) void attention_kernel(const float* __restrict__ nodes,
                                                        float* __restrict__ dout,
                                                        int final_iter) {
    extern __shared__ float sh[];
    float* cache = sh;                       // CAP*256
    float* ebuf  = sh + CAP * 256;           // CAP
    float* qs    = ebuf + CAP;               // 256
    float* red   = qs + 256;                 // 16
    float* part  = red + 16;                 // 256
    __shared__ float s_max, s_inv;

    int g = blockIdx.x;
    int s = d_starts[g], en = d_starts[g + 1];
    int len = en - s;
    int tid = threadIdx.x, lane = tid & 31, w = tid >> 5;

    if (tid < 256) qs[tid] = d_q[(size_t)g * 256 + tid];
    __syncthreads();

    const float4* q4 = (const float4*)qs;
    float4 q0 = q4[lane], q1 = q4[32 + lane];
    const float4* n4 = (const float4*)nodes;

    bool cached = (len <= CAP);
    float lmax = -3.4e38f;

    // ---- phase 1: load rows (pipelined), dot with q, stash e ----
    {
        int li = w;
        float4 a0, a1;
        if (li < len) {
            size_t n = (size_t)(s + li) * 64;
            a0 = n4[n + lane]; a1 = n4[n + 32 + lane];
        }
        while (li < len) {
            int lj = li + 16;
            float4 b0, b1;
            if (lj < len) {
                size_t n = (size_t)(s + lj) * 64;
                b0 = n4[n + lane]; b1 = n4[n + 32 + lane];
            }
            if (cached) {
                ((float4*)cache)[li * 64 + lane] = a0;
                ((float4*)cache)[li * 64 + 32 + lane] = a1;
            }
            float d = a0.x * q0.x + a0.y * q0.y + a0.z * q0.z + a0.w * q0.w
                    + a1.x * q1.x + a1.y * q1.y + a1.z * q1.z + a1.w * q1.w;
            #pragma unroll
            for (int o = 16; o; o >>= 1) d += __shfl_xor_sync(0xffffffffu, d, o);
            if (lane == 0) {
                if (cached) ebuf[li] = d; else d_e[s + li] = d;
            }
            lmax = fmaxf(lmax, d);
            a0 = b0; a1 = b1; li = lj;
        }
    }
    if (lane == 0) red[w] = lmax;
    __syncthreads();
    if (tid == 0) {
        float m = red[0];
        #pragma unroll
        for (int i = 1; i < 16; i++) m = fmaxf(m, red[i]);
        s_max = m;
    }
    __syncthreads();
    float gm = s_max;

    // ---- phase 2: exp + sum ----
    float lsum = 0.f;
    if (cached) {
        for (int li = tid; li < len; li += 512) {
            float ex = expf(ebuf[li] - gm);
            ebuf[li] = ex;
            lsum += ex;
        }
    } else {
        for (int li = tid; li < len; li += 512) {
            float ex = expf(d_e[s + li] - gm);
            d_e[s + li] = ex;
            lsum += ex;
        }
    }
    #pragma unroll
    for (int o = 16; o; o >>= 1) lsum += __shfl_xor_sync(0xffffffffu, lsum, o);
    if (lane == 0) red[w] = lsum;
    __syncthreads();
    if (tid == 0) {
        float sd = 0.f;
        #pragma unroll
        for (int i = 0; i < 16; i++) sd += red[i];
        s_inv = (sd > 0.f) ? 1.f / sd : 0.f;
    }
    __syncthreads();
    float inv = s_inv;

    // ---- phase 3: r[t] = sum_li a_li * row_li[t]  (two row-halves) ----
    int t = tid & 255, half = tid >> 8;
    float acc0 = 0.f, acc1 = 0.f;
    if (cached) {
        int li = half;
        for (; li + 2 < len; li += 4) {
            acc0 = fmaf(ebuf[li],     cache[li * 256 + t],       acc0);
            acc1 = fmaf(ebuf[li + 2], cache[(li + 2) * 256 + t], acc1);
        }
        for (; li < len; li += 2) acc0 = fmaf(ebuf[li], cache[li * 256 + t], acc0);
    } else {
        int li = half;
        for (; li + 2 < len; li += 4) {
            acc0 = fmaf(d_e[s + li],     nodes[(size_t)(s + li) * 256 + t],     acc0);
            acc1 = fmaf(d_e[s + li + 2], nodes[(size_t)(s + li + 2) * 256 + t], acc1);
        }
        for (; li < len; li += 2) acc0 = fmaf(d_e[s + li], nodes[(size_t)(s + li) * 256 + t], acc0);
    }
    float acc = acc0 + acc1;
    if (half) part[t] = acc;
    __syncthreads();
    if (tid < 256) {
        acc = (acc + part[tid]) * inv;
        float qv = qs[tid];
        if (final_iter) {
            dout[(size_t)g * 512 + tid] = qv;
            dout[(size_t)g * 512 + 256 + tid] = acc;
        } else {
            __nv_bfloat16 h, l;
            split_bf16(qv, h, l);
            d_X0h[(size_t)g * 768 + tid] = h;
            d_X0l[(size_t)g * 768 + tid] = l;
            split_bf16(acc, h, l);
            d_X0h[(size_t)g * 768 + 256 + tid] = h;
            d_X0l[(size_t)g * 768 + 256 + tid] = l;
        }
    }
}

// ---------------- mma.sync bf16-split GEMM: gates[M,1024] = X[M,K] * W[1024,K]^T ----
// CTA tile 128x128, 8 warps (4m x 2n), warp tile 32x64, BK=32, 3-stage cp.async.
#define ROWB 80                    // padded row bytes (conflict-free ldmatrix)
#define ARR  (128 * ROWB)          // 10240 B per array
#define STG  (4 * ARR)             // 40960 B per stage
#define SMEM_GEMM (3 * STG)        // 122880 B

__global__ __launch_bounds__(256, 1) void mma_gates(int layer, int B) {
    const __nv_bfloat16* __restrict__ Agh = layer ? d_X1h : d_X0h;
    const __nv_bfloat16* __restrict__ Agl = layer ? d_X1l : d_X0l;
    const __nv_bfloat16* __restrict__ Wgh = layer ? d_W1h : d_W0h;
    const __nv_bfloat16* __restrict__ Wgl = layer ? d_W1l : d_W0l;
    const int K = layer ? 512 : 768;

    extern __shared__ __nv_bfloat16 sm[];
    const uint32_t sbase = smem_u32(sm);

    const int tid = threadIdx.x, lane = tid & 31, warp = tid >> 5;
    const int wm = warp >> 1, wn = warp & 1;
    const int tm = blockIdx.y, tn = blockIdx.x;

    float c[2][8][4];
    #pragma unroll
    for (int i = 0; i < 2; i++)
        #pragma unroll
        for (int j = 0; j < 8; j++)
            #pragma unroll
            for (int k = 0; k < 4; k++) c[i][j][k] = 0.f;

    int idx0 = tid, idx1 = tid + 256;
    int row0 = idx0 >> 2, ch0 = idx0 & 3;
    int row1 = idx1 >> 2, ch1 = idx1 & 3;
    int ar0 = tm * 128 + row0; if (ar0 >= B) ar0 = B - 1;
    int ar1 = tm * 128 + row1; if (ar1 >= B) ar1 = B - 1;
    int br0 = tn * 128 + row0;
    int br1 = tn * 128 + row1;

    const int niter = K >> 5;

    #define ISSUE(I, BUF) do {                                                   \
        int _k0 = (I) << 5;                                                      \
        uint32_t _d0 = sbase + (BUF) * STG + row0 * ROWB + ch0 * 16;             \
        uint32_t _d1 = sbase + (BUF) * STG + row1 * ROWB + ch1 * 16;             \
        size_t _a0 = (size_t)ar0 * K + _k0 + ch0 * 8;                            \
        size_t _a1 = (size_t)ar1 * K + _k0 + ch1 * 8;                            \
        size_t _b0 = (size_t)br0 * K + _k0 + ch0 * 8;                            \
        size_t _b1 = (size_t)br1 * K + _k0 + ch1 * 8;                            \
        cp16(_d0 + 0 * ARR, Agh + _a0);  cp16(_d1 + 0 * ARR, Agh + _a1);         \
        cp16(_d0 + 1 * ARR, Agl + _a0);  cp16(_d1 + 1 * ARR, Agl + _a1);         \
        cp16(_d0 + 2 * ARR, Wgh + _b0);  cp16(_d1 + 2 * ARR, Wgh + _b1);         \
        cp16(_d0 + 3 * ARR, Wgl + _b0);  cp16(_d1 + 3 * ARR, Wgl + _b1);         \
        CP_COMMIT();                                                             \
    } while (0)

    ISSUE(0, 0);
    ISSUE(1, 1);

    const int m0 = wm * 32, n0 = wn * 64;
    const uint32_t a_row = m0 + (lane & 15);
    const uint32_t a_koff = (lane >> 4) * 16;
    const uint32_t b_row = n0 + (lane & 7) + ((lane >> 4) << 3);
    const uint32_t b_koff = ((lane >> 3) & 1) * 16;

    int buf = 0, nbuf = 2;
    for (int i = 0; i < niter; i++) {
        if (i + 1 < niter) CP_WAIT1(); else CP_WAIT0();
        __syncthreads();
        if (i + 2 < niter) {
            ISSUE(i + 2, nbuf);
        }

        uint32_t sb = sbase + buf * STG;
        uint32_t aAh = sb + 0 * ARR, aAl = sb + 1 * ARR;
        uint32_t aBh = sb + 2 * ARR, aBl = sb + 3 * ARR;

        #pragma unroll
        for (int kk = 0; kk < 2; kk++) {
            uint32_t kb = kk * 32;
            uint32_t ah[2][4], al[2][4], bh[4][4], bl[4][4];
            ldsm4(ah[0], aAh + a_row * ROWB + kb + a_koff);
            ldsm4(ah[1], aAh + (a_row + 16) * ROWB + kb + a_koff);
            ldsm4(al[0], aAl + a_row * ROWB + kb + a_koff);
            ldsm4(al[1], aAl + (a_row + 16) * ROWB + kb + a_koff);
            #pragma unroll
            for (int nb = 0; nb < 4; nb++) {
                ldsm4(bh[nb], aBh + (b_row + nb * 16) * ROWB + kb + b_koff);
                ldsm4(bl[nb], aBl + (b_row + nb * 16) * ROWB + kb + b_koff);
            }
            #pragma unroll
            for (int mi = 0; mi < 2; mi++)
                #pragma unroll
                for (int nb = 0; nb < 4; nb++)
                    #pragma unroll
                    for (int h = 0; h < 2; h++) {
                        int n8 = nb * 2 + h;
                        mma16816(c[mi][n8], ah[mi], &bh[nb][h * 2]);   // hi*hi
                        mma16816(c[mi][n8], ah[mi], &bl[nb][h * 2]);   // hi*lo
                        mma16816(c[mi][n8], al[mi], &bh[nb][h * 2]);   // lo*hi
                    }
        }
        buf = (buf == 2) ? 0 : buf + 1;
        nbuf = (nbuf == 2) ? 0 : nbuf + 1;
    }

    // epilogue: write fp32 gates
    int g = lane >> 2, qt = lane & 3;
    #pragma unroll
    for (int mi = 0; mi < 2; mi++) {
        #pragma unroll
        for (int n8 = 0; n8 < 8; n8++) {
            int row = tm * 128 + m0 + mi * 16 + g;
            int col = tn * 128 + n0 + n8 * 8 + qt * 2;
            if (row < B)
                *(float2*)&d_gates[(size_t)row * 1024 + col] = make_float2(c[mi][n8][0], c[mi][n8][1]);
            if (row + 8 < B)
                *(float2*)&d_gates[(size_t)(row + 8) * 1024 + col] = make_float2(c[mi][n8][2], c[mi][n8][3]);
        }
    }
    #undef ISSUE
}

// ---------------- LSTM pointwise: gates -> (h, c), writes bf16 split inputs ----
__global__ void lstm_act_kernel(int layer, int B) {
    int idx = blockIdx.x * blockDim.x + threadIdx.x;
    if (idx >= B * 256) return;
    int b = idx >> 8, t = idx & 255;
    const float* gr = d_gates + (size_t)b * 1024;
    const float* bs = (layer == 0) ? d_b0 : d_b1;
    float* c = (layer == 0) ? d_c0 : d_c1;

    float gi = gr[t]       + bs[t];
    float gf = gr[t + 256] + bs[t + 256];
    float gg = gr[t + 512] + bs[t + 512];
    float go = gr[t + 768] + bs[t + 768];

    float si = 1.f / (1.f + expf(-gi));
    float sf = 1.f / (1.f + expf(-gf));
    float tg = tanhf(gg);
    float so = 1.f / (1.f + expf(-go));

    float cn = sf * c[idx] + si * tg;
    c[idx] = cn;
    float hn = so * tanhf(cn);

    __nv_bfloat16 h, l;
    split_bf16(hn, h, l);
    if (layer == 0) {
        d_X0h[(size_t)b * 768 + 512 + t] = h;
        d_X0l[(size_t)b * 768 + 512 + t] = l;
        d_X1h[(size_t)b * 512 + t]       = h;
        d_X1l[(size_t)b * 512 + t]       = l;
    } else {
        d_X1h[(size_t)b * 512 + 256 + t] = h;
        d_X1l[(size_t)b * 512 + 256 + t] = l;
        d_q[idx] = hn;
    }
}

// ---------------- host launcher ----------------
extern "C" void kernel_launch(void* const* d_in, const int* in_sizes, int n_in,
                              void* d_out, int out_size) {
    const float* nodes = (const float*)d_in[0];
    const void*  gid   = d_in[1];
    int N = in_sizes[1];

    int wbase = (in_sizes[2] == 1) ? 3 : 2;
    const float* Wih0 = (const float*)d_in[wbase + 0];
    const float* Whh0 = (const float*)d_in[wbase + 1];
    const float* bih0 = (const float*)d_in[wbase + 2];
    const float* bhh0 = (const float*)d_in[wbase + 3];
    const float* Wih1 = (const float*)d_in[wbase + 4];
    const float* Whh1 = (const float*)d_in[wbase + 5];
    const float* bih1 = (const float*)d_in[wbase + 6];
    const float* bhh1 = (const float*)d_in[wbase + 7];

    int B = out_size / (2 * Hh);
    float* out = (float*)d_out;

    cudaFuncSetAttribute(mma_gates, cudaFuncAttributeMaxDynamicSharedMemorySize, SMEM_GEMM);
    cudaFuncSetAttribute(attention_kernel, cudaFuncAttributeMaxDynamicSharedMemorySize, ATT_SMEM);

    detect_kernel<<<1, 1>>>((const int*)gid, N);
    starts_kernel<<<(B + 1 + 255) / 256, 256>>>(gid, N, B);
    pack_kernel<<<(1024 * 768 + 255) / 256, 256>>>(Wih0, Whh0, bih0, bhh0,
                                                   Wih1, Whh1, bih1, bhh1);
    init_kernel<<<(B * 768 + 255) / 256, 256>>>(B);

    dim3 gemm_grid(1024 / 128, (B + 127) / 128);
    const int M_ITERS = 6;
    for (int i = 0; i < M_ITERS; i++) {
        int final_iter = (i == M_ITERS - 1) ? 1 : 0;
        attention_kernel<<<B, 512, ATT_SMEM>>>(nodes, out, final_iter);
        if (!final_iter) {
            mma_gates<<<gemm_grid, 256, SMEM_GEMM>>>(0, B);
            lstm_act_kernel<<<(B * 256 + 255) / 256, 256>>>(0, B);
            mma_gates<<<gemm_grid, 256, SMEM_GEMM>>>(1, B);
            lstm_act_kernel<<<(B * 256 + 255) / 256, 256>>>(1, B);
        }
    }
}

// round 6
// speedup vs baseline: 1.1508x; 1.1508x over previous
#include <cuda_runtime.h>
#include <cuda_bf16.h>
#include <math.h>
#include <stdint.h>

#define Hh 256
#define NMAX 262144
#define BMAX 4096

// ---------------- device scratch (no allocations allowed) ----------------
__device__ float d_e[NMAX];
__device__ int   d_starts[BMAX + 1];
__device__ int   d_is64;
__device__ float d_q[BMAX * 256];            // q = h1 (fp32, for attention)
__device__ float d_c0[BMAX * 256];
__device__ float d_c1[BMAX * 256];
// bf16 split operands for GEMMs
__device__ __nv_bfloat16 d_X0h[BMAX * 768], d_X0l[BMAX * 768];   // [q_star(512)|h0(256)]
__device__ __nv_bfloat16 d_X1h[BMAX * 512], d_X1l[BMAX * 512];   // [h0(256)|h1(256)]
__device__ __nv_bfloat16 d_W0h[1024 * 768], d_W0l[1024 * 768];   // gate-interleaved [Wih0|Whh0]
__device__ __nv_bfloat16 d_W1h[1024 * 512], d_W1l[1024 * 512];
__device__ float d_b0[1024], d_b1[1024];     // gate-interleaved bih+bhh

// ---------------- small helpers ----------------
__device__ __forceinline__ uint32_t smem_u32(const void* p) {
    uint32_t a;
    asm("{ .reg .u64 t; cvta.to.shared.u64 t, %1; cvt.u32.u64 %0, t; }" : "=r"(a) : "l"(p));
    return a;
}
__device__ __forceinline__ void cp16(uint32_t dst, const void* src) {
    asm volatile("cp.async.cg.shared.global [%0], [%1], 16;" :: "r"(dst), "l"(src));
}
#define CP_COMMIT() asm volatile("cp.async.commit_group;" ::: "memory")
#define CP_WAIT1()  asm volatile("cp.async.wait_group 1;" ::: "memory")
#define CP_WAIT0()  asm volatile("cp.async.wait_group 0;" ::: "memory")

__device__ __forceinline__ void ldsm4(uint32_t* r, uint32_t addr) {
    asm volatile("ldmatrix.sync.aligned.m8n8.x4.shared.b16 {%0,%1,%2,%3}, [%4];"
                 : "=r"(r[0]), "=r"(r[1]), "=r"(r[2]), "=r"(r[3]) : "r"(addr));
}
__device__ __forceinline__ void mma16816(float* c, const uint32_t* a, const uint32_t* b) {
    asm volatile(
        "mma.sync.aligned.m16n8k16.row.col.f32.bf16.bf16.f32 "
        "{%0,%1,%2,%3},{%4,%5,%6,%7},{%8,%9},{%0,%1,%2,%3};"
        : "+f"(c[0]), "+f"(c[1]), "+f"(c[2]), "+f"(c[3])
        : "r"(a[0]), "r"(a[1]), "r"(a[2]), "r"(a[3]), "r"(b[0]), "r"(b[1]));
}
__device__ __forceinline__ void split_bf16(float x, __nv_bfloat16& h, __nv_bfloat16& l) {
    h = __float2bfloat16(x);
    l = __float2bfloat16(x - __bfloat162float(h));
}
__device__ __forceinline__ float sigmoidf_(float x) { return 1.f / (1.f + expf(-x)); }

// ---------------- graph_id dtype detection ----------------
__global__ void detect_kernel(const int* p, int N) {
    int z = 1;
    for (int j = 0; j < 8; j++) {
        int idx = N - 1 - 2 * j;
        if (idx < 1) break;
        if ((idx & 1) == 0) idx--;
        if (idx >= 1 && p[idx] != 0) z = 0;
    }
    d_is64 = z;
}
__device__ __forceinline__ int get_gid(const void* p, int i) {
    if (d_is64) return (int)((const long long*)p)[i];
    return ((const int*)p)[i];
}
__global__ void starts_kernel(const void* gid, int N, int B) {
    int g = blockIdx.x * blockDim.x + threadIdx.x;
    if (g > B) return;
    int lo = 0, hi = N;
    while (lo < hi) {
        int mid = (lo + hi) >> 1;
        if (get_gid(gid, mid) < g) lo = mid + 1; else hi = mid;
    }
    d_starts[g] = lo;
}

// ---------------- pack weights (bf16 split, gate-interleaved rows) ----------------
// packed row j' = 4*t + gate (gate: 0=i,1=f,2=g,3=o); original row = gate*256 + t
__global__ void pack_kernel(const float* __restrict__ Wih0, const float* __restrict__ Whh0,
                            const float* __restrict__ bih0, const float* __restrict__ bhh0,
                            const float* __restrict__ Wih1, const float* __restrict__ Whh1,
                            const float* __restrict__ bih1, const float* __restrict__ bhh1) {
    int i = blockIdx.x * blockDim.x + threadIdx.x;
    if (i < 1024 * 768) {
        int j = i / 768, k = i % 768;
        int oj = (j & 3) * 256 + (j >> 2);
        float v = (k < 512) ? Wih0[oj * 512 + k] : Whh0[oj * 256 + (k - 512)];
        split_bf16(v, d_W0h[i], d_W0l[i]);
    }
    if (i < 1024 * 512) {
        int j = i / 512, k = i % 512;
        int oj = (j & 3) * 256 + (j >> 2);
        float v = (k < 256) ? Wih1[oj * 256 + k] : Whh1[oj * 256 + (k - 256)];
        split_bf16(v, d_W1h[i], d_W1l[i]);
    }
    if (i < 1024) {
        int oi = (i & 3) * 256 + (i >> 2);
        d_b0[i] = bih0[oi] + bhh0[oi];
        d_b1[i] = bih1[oi] + bhh1[oi];
    }
}

// ---------------- zero-init state ----------------
__global__ void init_kernel(int B) {
    int i = blockIdx.x * blockDim.x + threadIdx.x;
    __nv_bfloat16 z = __float2bfloat16(0.f);
    if (i < B * 768) { d_X0h[i] = z; d_X0l[i] = z; }
    if (i < B * 512) { d_X1h[i] = z; d_X1l[i] = z; }
    if (i < B * 256) { d_c0[i] = 0.f; d_c1[i] = 0.f; d_q[i] = 0.f; }
}

// ---------------- attention (round-3 proven version) ----------------
__global__ void attention_kernel(const float* __restrict__ nodes,
                                 float* __restrict__ dout, int final_iter) {
    int g = blockIdx.x;
    int s = d_starts[g], en = d_starts[g + 1];
    __shared__ float qs[256];
    __shared__ float red[8];
    __shared__ float s_max, s_inv;
    int tid = threadIdx.x, lane = tid & 31, w = tid >> 5;

    qs[tid] = d_q[(size_t)g * 256 + tid];
    __syncthreads();

    float lmax = -3.4e38f;
    for (int n = s + w; n < en; n += 8) {
        const float* row = nodes + (size_t)n * 256;
        float d = 0.f;
        #pragma unroll
        for (int k = 0; k < 8; k++) d = fmaf(row[lane + 32 * k], qs[lane + 32 * k], d);
        #pragma unroll
        for (int o = 16; o; o >>= 1) d += __shfl_xor_sync(0xffffffffu, d, o);
        if (lane == 0) d_e[n] = d;
        lmax = fmaxf(lmax, d);
    }
    if (lane == 0) red[w] = lmax;
    __syncthreads();
    if (tid == 0) {
        float m = red[0];
        #pragma unroll
        for (int i = 1; i < 8; i++) m = fmaxf(m, red[i]);
        s_max = m;
    }
    __syncthreads();
    float gm = s_max;

    float lsum = 0.f;
    for (int n = s + tid; n < en; n += 256) {
        float ex = expf(d_e[n] - gm);
        d_e[n] = ex;
        lsum += ex;
    }
    #pragma unroll
    for (int o = 16; o; o >>= 1) lsum += __shfl_xor_sync(0xffffffffu, lsum, o);
    if (lane == 0) red[w] = lsum;
    __syncthreads();
    if (tid == 0) {
        float sd = 0.f;
        #pragma unroll
        for (int i = 0; i < 8; i++) sd += red[i];
        s_inv = (sd > 0.f) ? 1.f / sd : 0.f;
    }
    __syncthreads();
    float inv = s_inv;

    float a0 = 0.f, a1 = 0.f, a2 = 0.f, a3 = 0.f;
    int n = s;
    for (; n + 3 < en; n += 4) {
        a0 = fmaf(d_e[n + 0], nodes[(size_t)(n + 0) * 256 + tid], a0);
        a1 = fmaf(d_e[n + 1], nodes[(size_t)(n + 1) * 256 + tid], a1);
        a2 = fmaf(d_e[n + 2], nodes[(size_t)(n + 2) * 256 + tid], a2);
        a3 = fmaf(d_e[n + 3], nodes[(size_t)(n + 3) * 256 + tid], a3);
    }
    for (; n < en; n++) a0 = fmaf(d_e[n], nodes[(size_t)n * 256 + tid], a0);
    float acc = ((a0 + a1) + (a2 + a3)) * inv;

    if (final_iter) {
        dout[(size_t)g * 512 + tid] = qs[tid];
        dout[(size_t)g * 512 + 256 + tid] = acc;
    } else {
        __nv_bfloat16 h, l;
        split_bf16(qs[tid], h, l);
        d_X0h[(size_t)g * 768 + tid] = h;
        d_X0l[(size_t)g * 768 + tid] = l;
        split_bf16(acc, h, l);
        d_X0h[(size_t)g * 768 + 256 + tid] = h;
        d_X0l[(size_t)g * 768 + 256 + tid] = l;
    }
}

// ---------------- fused GEMM + LSTM cell ----------------
// gates = X * W^T (gate-interleaved cols), then in-epilogue LSTM pointwise.
// CTA tile 128x128, 8 warps (4m x 2n), warp tile 32x64, BK=32, 2-stage cp.async.
#define ROWB 80                    // padded row bytes (conflict-free ldmatrix)
#define ARR  (128 * ROWB)          // 10240 B per array
#define STG  (4 * ARR)             // 40960 B per stage
#define CSTRIDE 33
#define SMEM_GEMM (2 * STG + 512)  // + bias region

__global__ __launch_bounds__(256, 1) void mma_lstm(int layer, int B) {
    const __nv_bfloat16* __restrict__ Agh = layer ? d_X1h : d_X0h;
    const __nv_bfloat16* __restrict__ Agl = layer ? d_X1l : d_X0l;
    const __nv_bfloat16* __restrict__ Wgh = layer ? d_W1h : d_W0h;
    const __nv_bfloat16* __restrict__ Wgl = layer ? d_W1l : d_W0l;
    const float* __restrict__ bias = layer ? d_b1 : d_b0;
    float* __restrict__ cst = layer ? d_c1 : d_c0;
    const int K = layer ? 512 : 768;

    extern __shared__ char smc[];
    const uint32_t sbase = smem_u32(smc);
    float* bsm = (float*)(smc + 2 * STG);    // 128 floats

    const int tid = threadIdx.x, lane = tid & 31, warp = tid >> 5;
    const int wm = warp >> 1, wn = warp & 1;
    const int tm = blockIdx.y, tn = blockIdx.x;

    if (tid < 128) bsm[tid] = bias[tn * 128 + tid];

    float c[2][8][4];
    #pragma unroll
    for (int i = 0; i < 2; i++)
        #pragma unroll
        for (int j = 0; j < 8; j++)
            #pragma unroll
            for (int k = 0; k < 4; k++) c[i][j][k] = 0.f;

    int idx0 = tid, idx1 = tid + 256;
    int row0 = idx0 >> 2, ch0 = idx0 & 3;
    int row1 = idx1 >> 2, ch1 = idx1 & 3;
    int ar0 = tm * 128 + row0; if (ar0 >= B) ar0 = B - 1;
    int ar1 = tm * 128 + row1; if (ar1 >= B) ar1 = B - 1;
    int br0 = tn * 128 + row0;
    int br1 = tn * 128 + row1;

    const int niter = K >> 5;

    #define ISSUE(I, BUF) do {                                                   \
        int _k0 = (I) << 5;                                                      \
        uint32_t _d0 = sbase + (BUF) * STG + row0 * ROWB + ch0 * 16;             \
        uint32_t _d1 = sbase + (BUF) * STG + row1 * ROWB + ch1 * 16;             \
        size_t _a0 = (size_t)ar0 * K + _k0 + ch0 * 8;                            \
        size_t _a1 = (size_t)ar1 * K + _k0 + ch1 * 8;                            \
        size_t _b0 = (size_t)br0 * K + _k0 + ch0 * 8;                            \
        size_t _b1 = (size_t)br1 * K + _k0 + ch1 * 8;                            \
        cp16(_d0 + 0 * ARR, Agh + _a0);  cp16(_d1 + 0 * ARR, Agh + _a1);         \
        cp16(_d0 + 1 * ARR, Agl + _a0);  cp16(_d1 + 1 * ARR, Agl + _a1);         \
        cp16(_d0 + 2 * ARR, Wgh + _b0);  cp16(_d1 + 2 * ARR, Wgh + _b1);         \
        cp16(_d0 + 3 * ARR, Wgl + _b0);  cp16(_d1 + 3 * ARR, Wgl + _b1);         \
        CP_COMMIT();                                                             \
    } while (0)

    ISSUE(0, 0);

    const int m0 = wm * 32, n0 = wn * 64;
    const uint32_t a_row = m0 + (lane & 15);
    const uint32_t a_koff = (lane >> 4) * 16;
    const uint32_t b_row = n0 + (lane & 7) + ((lane >> 4) << 3);
    const uint32_t b_koff = ((lane >> 3) & 1) * 16;

    for (int i = 0; i < niter; i++) {
        int buf = i & 1;
        if (i + 1 < niter) { ISSUE(i + 1, buf ^ 1); CP_WAIT1(); }
        else               { CP_WAIT0(); }
        __syncthreads();

        uint32_t sb = sbase + buf * STG;
        uint32_t aAh = sb + 0 * ARR, aAl = sb + 1 * ARR;
        uint32_t aBh = sb + 2 * ARR, aBl = sb + 3 * ARR;

        #pragma unroll
        for (int kk = 0; kk < 2; kk++) {
            uint32_t kb = kk * 32;
            uint32_t ah[2][4], al[2][4], bh[4][4], bl[4][4];
            ldsm4(ah[0], aAh + a_row * ROWB + kb + a_koff);
            ldsm4(ah[1], aAh + (a_row + 16) * ROWB + kb + a_koff);
            ldsm4(al[0], aAl + a_row * ROWB + kb + a_koff);
            ldsm4(al[1], aAl + (a_row + 16) * ROWB + kb + a_koff);
            #pragma unroll
            for (int nb = 0; nb < 4; nb++) {
                ldsm4(bh[nb], aBh + (b_row + nb * 16) * ROWB + kb + b_koff);
                ldsm4(bl[nb], aBl + (b_row + nb * 16) * ROWB + kb + b_koff);
            }
            #pragma unroll
            for (int mi = 0; mi < 2; mi++)
                #pragma unroll
                for (int nb = 0; nb < 4; nb++)
                    #pragma unroll
                    for (int h = 0; h < 2; h++) {
                        int n8 = nb * 2 + h;
                        mma16816(c[mi][n8], ah[mi], &bh[nb][h * 2]);   // hi*hi
                        mma16816(c[mi][n8], ah[mi], &bl[nb][h * 2]);   // hi*lo
                        mma16816(c[mi][n8], al[mi], &bh[nb][h * 2]);   // lo*hi
                    }
        }
        __syncthreads();
    }

    // ================= fused LSTM epilogue =================
    // CTA covers rows [tm*128, +128) and t-range [tn*32, +32).
    float* csta = (float*)smc;                         // [128][33]
    float* hsta = (float*)smc + 128 * CSTRIDE;         // [128][33]

    // stage c_old coalesced
    for (int idx = tid; idx < 128 * 32; idx += 256) {
        int r = idx >> 5, t = idx & 31;
        int row = tm * 128 + r;
        float v = (row < B) ? cst[(size_t)row * 256 + tn * 32 + t] : 0.f;
        csta[r * CSTRIDE + t] = v;
    }
    __syncthreads();

    // per-lane gate compute. Even qt lanes hold (i,f), odd hold (g,o); exchange.
    int g = lane >> 2, qt = lane & 3;
    #pragma unroll
    for (int mi = 0; mi < 2; mi++) {
        #pragma unroll
        for (int n8 = 0; n8 < 8; n8++) {
            float x0 = __shfl_xor_sync(0xffffffffu, c[mi][n8][0], 1);
            float x1 = __shfl_xor_sync(0xffffffffu, c[mi][n8][1], 1);
            float x2 = __shfl_xor_sync(0xffffffffu, c[mi][n8][2], 1);
            float x3 = __shfl_xor_sync(0xffffffffu, c[mi][n8][3], 1);
            int tl = wn * 16 + n8 * 2 + (qt >> 1);
            float ii, ff, gg, oo; int rl;
            if ((qt & 1) == 0) {
                ii = c[mi][n8][0]; ff = c[mi][n8][1]; gg = x0; oo = x1;
                rl = m0 + mi * 16 + g;
            } else {
                ii = x2; ff = x3; gg = c[mi][n8][2]; oo = c[mi][n8][3];
                rl = m0 + mi * 16 + g + 8;
            }
            ii += bsm[4 * tl + 0]; ff += bsm[4 * tl + 1];
            gg += bsm[4 * tl + 2]; oo += bsm[4 * tl + 3];
            float si = sigmoidf_(ii), sf = sigmoidf_(ff);
            float tg = tanhf(gg),    so = sigmoidf_(oo);
            float cold = csta[rl * CSTRIDE + tl];
            float cn = sf * cold + si * tg;
            float hn = so * tanhf(cn);
            csta[rl * CSTRIDE + tl] = cn;
            hsta[rl * CSTRIDE + tl] = hn;
        }
    }
    __syncthreads();

    // coalesced writeback: each thread handles 16 t's of one row-half
    {
        int r = tid >> 1, tseg = (tid & 1) * 16;
        int row = tm * 128 + r;
        if (row < B) {
            int tbase = tn * 32 + tseg;
            float cv[16], hv[16];
            #pragma unroll
            for (int j = 0; j < 16; j++) {
                cv[j] = csta[r * CSTRIDE + tseg + j];
                hv[j] = hsta[r * CSTRIDE + tseg + j];
            }
            float* cp = cst + (size_t)row * 256 + tbase;
            #pragma unroll
            for (int j = 0; j < 4; j++)
                *(float4*)(cp + j * 4) = make_float4(cv[j*4], cv[j*4+1], cv[j*4+2], cv[j*4+3]);

            __nv_bfloat16 hh[16], hl[16];
            #pragma unroll
            for (int j = 0; j < 16; j++) split_bf16(hv[j], hh[j], hl[j]);

            if (layer == 0) {
                __nv_bfloat16* p0h = d_X0h + (size_t)row * 768 + 512 + tbase;
                __nv_bfloat16* p0l = d_X0l + (size_t)row * 768 + 512 + tbase;
                __nv_bfloat16* p1h = d_X1h + (size_t)row * 512 + tbase;
                __nv_bfloat16* p1l = d_X1l + (size_t)row * 512 + tbase;
                *(uint4*)(p0h) = *(uint4*)(hh);  *(uint4*)(p0h + 8) = *(uint4*)(hh + 8);
                *(uint4*)(p0l) = *(uint4*)(hl);  *(uint4*)(p0l + 8) = *(uint4*)(hl + 8);
                *(uint4*)(p1h) = *(uint4*)(hh);  *(uint4*)(p1h + 8) = *(uint4*)(hh + 8);
                *(uint4*)(p1l) = *(uint4*)(hl);  *(uint4*)(p1l + 8) = *(uint4*)(hl + 8);
            } else {
                __nv_bfloat16* p1h = d_X1h + (size_t)row * 512 + 256 + tbase;
                __nv_bfloat16* p1l = d_X1l + (size_t)row * 512 + 256 + tbase;
                *(uint4*)(p1h) = *(uint4*)(hh);  *(uint4*)(p1h + 8) = *(uint4*)(hh + 8);
                *(uint4*)(p1l) = *(uint4*)(hl);  *(uint4*)(p1l + 8) = *(uint4*)(hl + 8);
                float* qp = d_q + (size_t)row * 256 + tbase;
                #pragma unroll
                for (int j = 0; j < 4; j++)
                    *(float4*)(qp + j * 4) = make_float4(hv[j*4], hv[j*4+1], hv[j*4+2], hv[j*4+3]);
            }
        }
    }
    #undef ISSUE
}

// ---------------- host launcher ----------------
extern "C" void kernel_launch(void* const* d_in, const int* in_sizes, int n_in,
                              void* d_out, int out_size) {
    const float* nodes = (const float*)d_in[0];
    const void*  gid   = d_in[1];
    int N = in_sizes[1];

    int wbase = (in_sizes[2] == 1) ? 3 : 2;
    const float* Wih0 = (const float*)d_in[wbase + 0];
    const float* Whh0 = (const float*)d_in[wbase + 1];
    const float* bih0 = (const float*)d_in[wbase + 2];
    const float* bhh0 = (const float*)d_in[wbase + 3];
    const float* Wih1 = (const float*)d_in[wbase + 4];
    const float* Whh1 = (const float*)d_in[wbase + 5];
    const float* bih1 = (const float*)d_in[wbase + 6];
    const float* bhh1 = (const float*)d_in[wbase + 7];

    int B = out_size / (2 * Hh);
    float* out = (float*)d_out;

    cudaFuncSetAttribute(mma_lstm, cudaFuncAttributeMaxDynamicSharedMemorySize, SMEM_GEMM);

    detect_kernel<<<1, 1>>>((const int*)gid, N);
    starts_kernel<<<(B + 1 + 255) / 256, 256>>>(gid, N, B);
    pack_kernel<<<(1024 * 768 + 255) / 256, 256>>>(Wih0, Whh0, bih0, bhh0,
                                                   Wih1, Whh1, bih1, bhh1);
    init_kernel<<<(B * 768 + 255) / 256, 256>>>(B);

    dim3 gemm_grid(1024 / 128, (B + 127) / 128);
    const int M_ITERS = 6;
    for (int i = 0; i < M_ITERS; i++) {
        int final_iter = (i == M_ITERS - 1) ? 1 : 0;
        attention_kernel<<<B, 256>>>(nodes, out, final_iter);
        if (!final_iter) {
            mma_lstm<<<gemm_grid, 256, SMEM_GEMM>>>(0, B);
            mma_lstm<<<gemm_grid, 256, SMEM_GEMM>>>(1, B);
        }
    }
}

// round 7
// speedup vs baseline: 1.4412x; 1.2523x over previous
#include <cuda_runtime.h>
#include <cuda_bf16.h>
#include <math.h>
#include <stdint.h>

#define Hh 256
#define NMAX 262144
#define BMAX 4096

// ---------------- device scratch (no allocations allowed) ----------------
__device__ int   d_starts[BMAX + 1];
__device__ int   d_is64;
__device__ float d_q[BMAX * 256];            // q = h1 (fp32, for attention)
__device__ float d_gates[BMAX * 1024];
__device__ float d_c0[BMAX * 256];
__device__ float d_c1[BMAX * 256];
// bf16 split operands for GEMMs
__device__ __nv_bfloat16 d_X0h[BMAX * 768], d_X0l[BMAX * 768];   // [q_star(512)|h0(256)]
__device__ __nv_bfloat16 d_X1h[BMAX * 512], d_X1l[BMAX * 512];   // [h0(256)|h1(256)]
__device__ __nv_bfloat16 d_W0h[1024 * 768], d_W0l[1024 * 768];   // [Wih0|Whh0]
__device__ __nv_bfloat16 d_W1h[1024 * 512], d_W1l[1024 * 512];   // [Wih1|Whh1]
__device__ float d_b0[1024], d_b1[1024];

// ---------------- small helpers ----------------
__device__ __forceinline__ uint32_t smem_u32(const void* p) {
    uint32_t a;
    asm("{ .reg .u64 t; cvta.to.shared.u64 t, %1; cvt.u32.u64 %0, t; }" : "=r"(a) : "l"(p));
    return a;
}
__device__ __forceinline__ void cp16(uint32_t dst, const void* src) {
    asm volatile("cp.async.cg.shared.global [%0], [%1], 16;" :: "r"(dst), "l"(src));
}
#define CP_COMMIT() asm volatile("cp.async.commit_group;" ::: "memory")
#define CP_WAIT1()  asm volatile("cp.async.wait_group 1;" ::: "memory")
#define CP_WAIT0()  asm volatile("cp.async.wait_group 0;" ::: "memory")

__device__ __forceinline__ void ldsm4(uint32_t* r, uint32_t addr) {
    asm volatile("ldmatrix.sync.aligned.m8n8.x4.shared.b16 {%0,%1,%2,%3}, [%4];"
                 : "=r"(r[0]), "=r"(r[1]), "=r"(r[2]), "=r"(r[3]) : "r"(addr));
}
__device__ __forceinline__ void mma16816(float* c, const uint32_t* a, const uint32_t* b) {
    asm volatile(
        "mma.sync.aligned.m16n8k16.row.col.f32.bf16.bf16.f32 "
        "{%0,%1,%2,%3},{%4,%5,%6,%7},{%8,%9},{%0,%1,%2,%3};"
        : "+f"(c[0]), "+f"(c[1]), "+f"(c[2]), "+f"(c[3])
        : "r"(a[0]), "r"(a[1]), "r"(a[2]), "r"(a[3]), "r"(b[0]), "r"(b[1]));
}
__device__ __forceinline__ void split_bf16(float x, __nv_bfloat16& h, __nv_bfloat16& l) {
    h = __float2bfloat16(x);
    l = __float2bfloat16(x - __bfloat162float(h));
}

// ---------------- graph_id dtype detection ----------------
__global__ void detect_kernel(const int* p, int N) {
    int z = 1;
    for (int j = 0; j < 8; j++) {
        int idx = N - 1 - 2 * j;
        if (idx < 1) break;
        if ((idx & 1) == 0) idx--;
        if (idx >= 1 && p[idx] != 0) z = 0;
    }
    d_is64 = z;
}
__device__ __forceinline__ int get_gid(const void* p, int i) {
    if (d_is64) return (int)((const long long*)p)[i];
    return ((const int*)p)[i];
}
__global__ void starts_kernel(const void* gid, int N, int B) {
    int g = blockIdx.x * blockDim.x + threadIdx.x;
    if (g > B) return;
    int lo = 0, hi = N;
    while (lo < hi) {
        int mid = (lo + hi) >> 1;
        if (get_gid(gid, mid) < g) lo = mid + 1; else hi = mid;
    }
    d_starts[g] = lo;
}

// ---------------- pack weights (bf16 split) + summed biases ----------------
__global__ void pack_kernel(const float* __restrict__ Wih0, const float* __restrict__ Whh0,
                            const float* __restrict__ bih0, const float* __restrict__ bhh0,
                            const float* __restrict__ Wih1, const float* __restrict__ Whh1,
                            const float* __restrict__ bih1, const float* __restrict__ bhh1) {
    int i = blockIdx.x * blockDim.x + threadIdx.x;
    if (i < 1024 * 768) {
        int j = i / 768, k = i % 768;
        float v = (k < 512) ? Wih0[j * 512 + k] : Whh0[j * 256 + (k - 512)];
        split_bf16(v, d_W0h[i], d_W0l[i]);
    }
    if (i < 1024 * 512) {
        int j = i / 512, k = i % 512;
        float v = (k < 256) ? Wih1[j * 256 + k] : Whh1[j * 256 + (k - 256)];
        split_bf16(v, d_W1h[i], d_W1l[i]);
    }
    if (i < 1024) {
        d_b0[i] = bih0[i] + bhh0[i];
        d_b1[i] = bih1[i] + bhh1[i];
    }
}

// ---------------- zero-init state ----------------
__global__ void init_kernel(int B) {
    int i = blockIdx.x * blockDim.x + threadIdx.x;
    __nv_bfloat16 z = __float2bfloat16(0.f);
    if (i < B * 768) { d_X0h[i] = z; d_X0l[i] = z; }
    if (i < B * 512) { d_X1h[i] = z; d_X1l[i] = z; }
    if (i < B * 256) { d_c0[i] = 0.f; d_c1[i] = 0.f; d_q[i] = 0.f; }
}

// ---------------- attention: single-pass online softmax ----------------
// One CTA (256 threads, 8 warps) per graph. Each warp runs an independent
// online softmax over its rows (rows read ONCE); warp partials merged via smem.
__global__ void attention_kernel(const float* __restrict__ nodes,
                                 float* __restrict__ dout, int final_iter) {
    int g = blockIdx.x;
    int s = d_starts[g], en = d_starts[g + 1];
    __shared__ float qs[256];
    __shared__ float vsum[8][256];
    __shared__ float wm[8], ws[8], wscale[8];
    __shared__ float s_inv;
    int tid = threadIdx.x, lane = tid & 31, w = tid >> 5;

    qs[tid] = d_q[(size_t)g * 256 + tid];
    __syncthreads();

    float qv[8];
    #pragma unroll
    for (int k = 0; k < 8; k++) qv[k] = qs[lane + 32 * k];

    float m = -3.4e38f, ssum = 0.f;
    float v[8];
    #pragma unroll
    for (int k = 0; k < 8; k++) v[k] = 0.f;

    for (int n = s + w; n < en; n += 8) {
        const float* row = nodes + (size_t)n * 256;
        float x[8];
        #pragma unroll
        for (int k = 0; k < 8; k++) x[k] = row[lane + 32 * k];
        float d = 0.f;
        #pragma unroll
        for (int k = 0; k < 8; k++) d = fmaf(x[k], qv[k], d);
        #pragma unroll
        for (int o = 16; o; o >>= 1) d += __shfl_xor_sync(0xffffffffu, d, o);

        float mn = fmaxf(m, d);
        float scale = __expf(m - mn);    // 0 on first row (m=-inf)
        float e = __expf(d - mn);
        ssum = ssum * scale + e;
        #pragma unroll
        for (int k = 0; k < 8; k++) v[k] = fmaf(v[k], scale, e * x[k]);
        m = mn;
    }

    if (lane == 0) { wm[w] = m; ws[w] = ssum; }
    #pragma unroll
    for (int k = 0; k < 8; k++) vsum[w][lane + 32 * k] = v[k];
    __syncthreads();

    if (tid == 0) {
        float M = -3.4e38f;
        #pragma unroll
        for (int i = 0; i < 8; i++) if (ws[i] > 0.f) M = fmaxf(M, wm[i]);
        float S = 0.f;
        #pragma unroll
        for (int i = 0; i < 8; i++) {
            float sc = (ws[i] > 0.f) ? __expf(wm[i] - M) : 0.f;
            wscale[i] = sc;
            S += ws[i] * sc;
        }
        s_inv = (S > 0.f) ? 1.f / S : 0.f;
    }
    __syncthreads();

    float acc = 0.f;
    #pragma unroll
    for (int i = 0; i < 8; i++) acc = fmaf(vsum[i][tid], wscale[i], acc);
    acc *= s_inv;

    if (final_iter) {
        dout[(size_t)g * 512 + tid] = qs[tid];
        dout[(size_t)g * 512 + 256 + tid] = acc;
    } else {
        __nv_bfloat16 h, l;
        split_bf16(qs[tid], h, l);
        d_X0h[(size_t)g * 768 + tid] = h;
        d_X0l[(size_t)g * 768 + tid] = l;
        split_bf16(acc, h, l);
        d_X0h[(size_t)g * 768 + 256 + tid] = h;
        d_X0l[(size_t)g * 768 + 256 + tid] = l;
    }
}

// ---------------- mma.sync bf16-split GEMM (R3-proven): gates = X * W^T ----
// CTA tile 128x128, 8 warps (4m x 2n), warp tile 32x64, BK=32, 2-stage cp.async.
#define ROWB 80                    // padded row bytes (conflict-free ldmatrix)
#define ARR  (128 * ROWB)          // 10240 B per array
#define STG  (4 * ARR)             // 40960 B per stage
#define SMEM_GEMM (2 * STG)        // 81920 B

__global__ __launch_bounds__(256, 1) void mma_gates(int layer, int B) {
    const __nv_bfloat16* __restrict__ Agh = layer ? d_X1h : d_X0h;
    const __nv_bfloat16* __restrict__ Agl = layer ? d_X1l : d_X0l;
    const __nv_bfloat16* __restrict__ Wgh = layer ? d_W1h : d_W0h;
    const __nv_bfloat16* __restrict__ Wgl = layer ? d_W1l : d_W0l;
    const int K = layer ? 512 : 768;

    extern __shared__ __nv_bfloat16 sm[];
    const uint32_t sbase = smem_u32(sm);

    const int tid = threadIdx.x, lane = tid & 31, warp = tid >> 5;
    const int wm = warp >> 1, wn = warp & 1;
    const int tm = blockIdx.y, tn = blockIdx.x;

    float c[2][8][4];
    #pragma unroll
    for (int i = 0; i < 2; i++)
        #pragma unroll
        for (int j = 0; j < 8; j++)
            #pragma unroll
            for (int k = 0; k < 4; k++) c[i][j][k] = 0.f;

    int idx0 = tid, idx1 = tid + 256;
    int row0 = idx0 >> 2, ch0 = idx0 & 3;
    int row1 = idx1 >> 2, ch1 = idx1 & 3;
    int ar0 = tm * 128 + row0; if (ar0 >= B) ar0 = B - 1;
    int ar1 = tm * 128 + row1; if (ar1 >= B) ar1 = B - 1;
    int br0 = tn * 128 + row0;
    int br1 = tn * 128 + row1;

    const int niter = K >> 5;

    #define ISSUE(I, BUF) do {                                                   \
        int _k0 = (I) << 5;                                                      \
        uint32_t _d0 = sbase + (BUF) * STG + row0 * ROWB + ch0 * 16;             \
        uint32_t _d1 = sbase + (BUF) * STG + row1 * ROWB + ch1 * 16;             \
        size_t _a0 = (size_t)ar0 * K + _k0 + ch0 * 8;                            \
        size_t _a1 = (size_t)ar1 * K + _k0 + ch1 * 8;                            \
        size_t _b0 = (size_t)br0 * K + _k0 + ch0 * 8;                            \
        size_t _b1 = (size_t)br1 * K + _k0 + ch1 * 8;                            \
        cp16(_d0 + 0 * ARR, Agh + _a0);  cp16(_d1 + 0 * ARR, Agh + _a1);         \
        cp16(_d0 + 1 * ARR, Agl + _a0);  cp16(_d1 + 1 * ARR, Agl + _a1);         \
        cp16(_d0 + 2 * ARR, Wgh + _b0);  cp16(_d1 + 2 * ARR, Wgh + _b1);         \
        cp16(_d0 + 3 * ARR, Wgl + _b0);  cp16(_d1 + 3 * ARR, Wgl + _b1);         \
        CP_COMMIT();                                                             \
    } while (0)

    ISSUE(0, 0);

    const int m0 = wm * 32, n0 = wn * 64;
    const uint32_t a_row = m0 + (lane & 15);
    const uint32_t a_koff = (lane >> 4) * 16;
    const uint32_t b_row = n0 + (lane & 7) + ((lane >> 4) << 3);
    const uint32_t b_koff = ((lane >> 3) & 1) * 16;

    for (int i = 0; i < niter; i++) {
        int buf = i & 1;
        if (i + 1 < niter) { ISSUE(i + 1, buf ^ 1); CP_WAIT1(); }
        else               { CP_WAIT0(); }
        __syncthreads();

        uint32_t sb = sbase + buf * STG;
        uint32_t aAh = sb + 0 * ARR, aAl = sb + 1 * ARR;
        uint32_t aBh = sb + 2 * ARR, aBl = sb + 3 * ARR;

        #pragma unroll
        for (int kk = 0; kk < 2; kk++) {
            uint32_t kb = kk * 32;
            uint32_t ah[2][4], al[2][4], bh[4][4], bl[4][4];
            ldsm4(ah[0], aAh + a_row * ROWB + kb + a_koff);
            ldsm4(ah[1], aAh + (a_row + 16) * ROWB + kb + a_koff);
            ldsm4(al[0], aAl + a_row * ROWB + kb + a_koff);
            ldsm4(al[1], aAl + (a_row + 16) * ROWB + kb + a_koff);
            #pragma unroll
            for (int nb = 0; nb < 4; nb++) {
                ldsm4(bh[nb], aBh + (b_row + nb * 16) * ROWB + kb + b_koff);
                ldsm4(bl[nb], aBl + (b_row + nb * 16) * ROWB + kb + b_koff);
            }
            #pragma unroll
            for (int mi = 0; mi < 2; mi++)
                #pragma unroll
                for (int nb = 0; nb < 4; nb++)
                    #pragma unroll
                    for (int h = 0; h < 2; h++) {
                        int n8 = nb * 2 + h;
                        mma16816(c[mi][n8], ah[mi], &bh[nb][h * 2]);   // hi*hi
                        mma16816(c[mi][n8], ah[mi], &bl[nb][h * 2]);   // hi*lo
                        mma16816(c[mi][n8], al[mi], &bh[nb][h * 2]);   // lo*hi
                    }
        }
        __syncthreads();
    }

    // epilogue: write fp32 gates
    int g = lane >> 2, qt = lane & 3;
    #pragma unroll
    for (int mi = 0; mi < 2; mi++) {
        #pragma unroll
        for (int n8 = 0; n8 < 8; n8++) {
            int row = tm * 128 + m0 + mi * 16 + g;
            int col = tn * 128 + n0 + n8 * 8 + qt * 2;
            if (row < B)
                *(float2*)&d_gates[(size_t)row * 1024 + col] = make_float2(c[mi][n8][0], c[mi][n8][1]);
            if (row + 8 < B)
                *(float2*)&d_gates[(size_t)(row + 8) * 1024 + col] = make_float2(c[mi][n8][2], c[mi][n8][3]);
        }
    }
    #undef ISSUE
}

// ---------------- LSTM pointwise: gates -> (h, c), writes bf16 split inputs ----
__global__ void lstm_act_kernel(int layer, int B) {
    int idx = blockIdx.x * blockDim.x + threadIdx.x;
    if (idx >= B * 256) return;
    int b = idx >> 8, t = idx & 255;
    const float* gr = d_gates + (size_t)b * 1024;
    const float* bs = (layer == 0) ? d_b0 : d_b1;
    float* c = (layer == 0) ? d_c0 : d_c1;

    float gi = gr[t]       + bs[t];
    float gf = gr[t + 256] + bs[t + 256];
    float gg = gr[t + 512] + bs[t + 512];
    float go = gr[t + 768] + bs[t + 768];

    float si = 1.f / (1.f + expf(-gi));
    float sf = 1.f / (1.f + expf(-gf));
    float tg = tanhf(gg);
    float so = 1.f / (1.f + expf(-go));

    float cn = sf * c[idx] + si * tg;
    c[idx] = cn;
    float hn = so * tanhf(cn);

    __nv_bfloat16 h, l;
    split_bf16(hn, h, l);
    if (layer == 0) {
        d_X0h[(size_t)b * 768 + 512 + t] = h;
        d_X0l[(size_t)b * 768 + 512 + t] = l;
        d_X1h[(size_t)b * 512 + t]       = h;
        d_X1l[(size_t)b * 512 + t]       = l;
    } else {
        d_X1h[(size_t)b * 512 + 256 + t] = h;
        d_X1l[(size_t)b * 512 + 256 + t] = l;
        d_q[idx] = hn;
    }
}

// ---------------- host launcher ----------------
extern "C" void kernel_launch(void* const* d_in, const int* in_sizes, int n_in,
                              void* d_out, int out_size) {
    const float* nodes = (const float*)d_in[0];
    const void*  gid   = d_in[1];
    int N = in_sizes[1];

    int wbase = (in_sizes[2] == 1) ? 3 : 2;
    const float* Wih0 = (const float*)d_in[wbase + 0];
    const float* Whh0 = (const float*)d_in[wbase + 1];
    const float* bih0 = (const float*)d_in[wbase + 2];
    const float* bhh0 = (const float*)d_in[wbase + 3];
    const float* Wih1 = (const float*)d_in[wbase + 4];
    const float* Whh1 = (const float*)d_in[wbase + 5];
    const float* bih1 = (const float*)d_in[wbase + 6];
    const float* bhh1 = (const float*)d_in[wbase + 7];

    int B = out_size / (2 * Hh);
    float* out = (float*)d_out;

    cudaFuncSetAttribute(mma_gates, cudaFuncAttributeMaxDynamicSharedMemorySize, SMEM_GEMM);

    detect_kernel<<<1, 1>>>((const int*)gid, N);
    starts_kernel<<<(B + 1 + 255) / 256, 256>>>(gid, N, B);
    pack_kernel<<<(1024 * 768 + 255) / 256, 256>>>(Wih0, Whh0, bih0, bhh0,
                                                   Wih1, Whh1, bih1, bhh1);
    init_kernel<<<(B * 768 + 255) / 256, 256>>>(B);

    dim3 gemm_grid(1024 / 128, (B + 127) / 128);
    const int M_ITERS = 6;
    for (int i = 0; i < M_ITERS; i++) {
        int final_iter = (i == M_ITERS - 1) ? 1 : 0;
        attention_kernel<<<B, 256>>>(nodes, out, final_iter);
        if (!final_iter) {
            mma_gates<<<gemm_grid, 256, SMEM_GEMM>>>(0, B);
            lstm_act_kernel<<<(B * 256 + 255) / 256, 256>>>(0, B);
            mma_gates<<<gemm_grid, 256, SMEM_GEMM>>>(1, B);
            lstm_act_kernel<<<(B * 256 + 255) / 256, 256>>>(1, B);
        }
    }
}

// round 8
// speedup vs baseline: 1.4508x; 1.0067x over previous
#include <cuda_runtime.h>
#include <cuda_bf16.h>
#include <math.h>
#include <stdint.h>

#define Hh 256
#define NMAX 262144
#define BMAX 4096

// ---------------- device scratch (no allocations allowed) ----------------
__device__ int   d_starts[BMAX + 1];
__device__ int   d_is64;
__device__ float d_q[BMAX * 256];            // q = h1 (fp32, for attention)
__device__ float d_gates[BMAX * 1024];
__device__ float d_c0[BMAX * 256];
__device__ float d_c1[BMAX * 256];
// bf16 split operands for GEMMs
__device__ __nv_bfloat16 d_X0h[BMAX * 768], d_X0l[BMAX * 768];   // [q_star(512)|h0(256)]
__device__ __nv_bfloat16 d_X1h[BMAX * 512], d_X1l[BMAX * 512];   // [h0(256)|h1(256)]
__device__ __nv_bfloat16 d_W0h[1024 * 768], d_W0l[1024 * 768];   // [Wih0|Whh0]
__device__ __nv_bfloat16 d_W1h[1024 * 512], d_W1l[1024 * 512];   // [Wih1|Whh1]
__device__ float d_b0[1024], d_b1[1024];

// ---------------- small helpers ----------------
__device__ __forceinline__ uint32_t smem_u32(const void* p) {
    uint32_t a;
    asm("{ .reg .u64 t; cvta.to.shared.u64 t, %1; cvt.u32.u64 %0, t; }" : "=r"(a) : "l"(p));
    return a;
}
__device__ __forceinline__ void cp16(uint32_t dst, const void* src) {
    asm volatile("cp.async.cg.shared.global [%0], [%1], 16;" :: "r"(dst), "l"(src));
}
#define CP_COMMIT() asm volatile("cp.async.commit_group;" ::: "memory")
#define CP_WAIT1()  asm volatile("cp.async.wait_group 1;" ::: "memory")
#define CP_WAIT0()  asm volatile("cp.async.wait_group 0;" ::: "memory")

__device__ __forceinline__ void ldsm4(uint32_t* r, uint32_t addr) {
    asm volatile("ldmatrix.sync.aligned.m8n8.x4.shared.b16 {%0,%1,%2,%3}, [%4];"
                 : "=r"(r[0]), "=r"(r[1]), "=r"(r[2]), "=r"(r[3]) : "r"(addr));
}
__device__ __forceinline__ void mma16816(float* c, const uint32_t* a, const uint32_t* b) {
    asm volatile(
        "mma.sync.aligned.m16n8k16.row.col.f32.bf16.bf16.f32 "
        "{%0,%1,%2,%3},{%4,%5,%6,%7},{%8,%9},{%0,%1,%2,%3};"
        : "+f"(c[0]), "+f"(c[1]), "+f"(c[2]), "+f"(c[3])
        : "r"(a[0]), "r"(a[1]), "r"(a[2]), "r"(a[3]), "r"(b[0]), "r"(b[1]));
}
__device__ __forceinline__ void split_bf16(float x, __nv_bfloat16& h, __nv_bfloat16& l) {
    h = __float2bfloat16(x);
    l = __float2bfloat16(x - __bfloat162float(h));
}

// ---------------- graph_id dtype detection ----------------
__global__ void detect_kernel(const int* p, int N) {
    int z = 1;
    for (int j = 0; j < 8; j++) {
        int idx = N - 1 - 2 * j;
        if (idx < 1) break;
        if ((idx & 1) == 0) idx--;
        if (idx >= 1 && p[idx] != 0) z = 0;
    }
    d_is64 = z;
}
__device__ __forceinline__ int get_gid(const void* p, int i) {
    if (d_is64) return (int)((const long long*)p)[i];
    return ((const int*)p)[i];
}
__global__ void starts_kernel(const void* gid, int N, int B) {
    int g = blockIdx.x * blockDim.x + threadIdx.x;
    if (g > B) return;
    int lo = 0, hi = N;
    while (lo < hi) {
        int mid = (lo + hi) >> 1;
        if (get_gid(gid, mid) < g) lo = mid + 1; else hi = mid;
    }
    d_starts[g] = lo;
}

// ---------------- pack weights (bf16 split) + summed biases ----------------
__global__ void pack_kernel(const float* __restrict__ Wih0, const float* __restrict__ Whh0,
                            const float* __restrict__ bih0, const float* __restrict__ bhh0,
                            const float* __restrict__ Wih1, const float* __restrict__ Whh1,
                            const float* __restrict__ bih1, const float* __restrict__ bhh1) {
    int i = blockIdx.x * blockDim.x + threadIdx.x;
    if (i < 1024 * 768) {
        int j = i / 768, k = i % 768;
        float v = (k < 512) ? Wih0[j * 512 + k] : Whh0[j * 256 + (k - 512)];
        split_bf16(v, d_W0h[i], d_W0l[i]);
    }
    if (i < 1024 * 512) {
        int j = i / 512, k = i % 512;
        float v = (k < 256) ? Wih1[j * 256 + k] : Whh1[j * 256 + (k - 256)];
        split_bf16(v, d_W1h[i], d_W1l[i]);
    }
    if (i < 1024) {
        d_b0[i] = bih0[i] + bhh0[i];
        d_b1[i] = bih1[i] + bhh1[i];
    }
}

// ---------------- zero-init state ----------------
__global__ void init_kernel(int B) {
    int i = blockIdx.x * blockDim.x + threadIdx.x;
    __nv_bfloat16 z = __float2bfloat16(0.f);
    if (i < B * 768) { d_X0h[i] = z; d_X0l[i] = z; }
    if (i < B * 512) { d_X1h[i] = z; d_X1l[i] = z; }
    if (i < B * 256) { d_c0[i] = 0.f; d_c1[i] = 0.f; d_q[i] = 0.f; }
}

// ---------------- attention: single-pass online softmax (float4 loads) ----------------
// One CTA (256 threads, 8 warps) per graph. Each warp runs an independent
// online softmax over its rows (rows read ONCE); warp partials merged via smem.
__global__ void attention_kernel(const float* __restrict__ nodes,
                                 float* __restrict__ dout, int final_iter) {
    int g = blockIdx.x;
    int s = d_starts[g], en = d_starts[g + 1];
    __shared__ float qs[256];
    __shared__ float vsum[8][256];
    __shared__ float wm[8], ws[8], wscale[8];
    __shared__ float s_inv;
    int tid = threadIdx.x, lane = tid & 31, w = tid >> 5;

    qs[tid] = d_q[(size_t)g * 256 + tid];
    __syncthreads();

    float4 q0 = ((const float4*)qs)[lane];
    float4 q1 = ((const float4*)qs)[32 + lane];

    float m = -3.4e38f, ssum = 0.f;
    float4 v0 = make_float4(0.f, 0.f, 0.f, 0.f);
    float4 v1 = make_float4(0.f, 0.f, 0.f, 0.f);

    for (int n = s + w; n < en; n += 8) {
        const float4* row4 = (const float4*)(nodes + (size_t)n * 256);
        float4 x0 = row4[lane];
        float4 x1 = row4[32 + lane];
        float d = x0.x * q0.x + x0.y * q0.y + x0.z * q0.z + x0.w * q0.w
                + x1.x * q1.x + x1.y * q1.y + x1.z * q1.z + x1.w * q1.w;
        #pragma unroll
        for (int o = 16; o; o >>= 1) d += __shfl_xor_sync(0xffffffffu, d, o);

        float mn = fmaxf(m, d);
        float scale = __expf(m - mn);    // 0 on first row (m=-inf)
        float e = __expf(d - mn);
        ssum = ssum * scale + e;
        v0.x = fmaf(v0.x, scale, e * x0.x); v0.y = fmaf(v0.y, scale, e * x0.y);
        v0.z = fmaf(v0.z, scale, e * x0.z); v0.w = fmaf(v0.w, scale, e * x0.w);
        v1.x = fmaf(v1.x, scale, e * x1.x); v1.y = fmaf(v1.y, scale, e * x1.y);
        v1.z = fmaf(v1.z, scale, e * x1.z); v1.w = fmaf(v1.w, scale, e * x1.w);
        m = mn;
    }

    if (lane == 0) { wm[w] = m; ws[w] = ssum; }
    ((float4*)vsum[w])[lane] = v0;
    ((float4*)vsum[w])[32 + lane] = v1;
    __syncthreads();

    if (tid == 0) {
        float M = -3.4e38f;
        #pragma unroll
        for (int i = 0; i < 8; i++) if (ws[i] > 0.f) M = fmaxf(M, wm[i]);
        float S = 0.f;
        #pragma unroll
        for (int i = 0; i < 8; i++) {
            float sc = (ws[i] > 0.f) ? __expf(wm[i] - M) : 0.f;
            wscale[i] = sc;
            S += ws[i] * sc;
        }
        s_inv = (S > 0.f) ? 1.f / S : 0.f;
    }
    __syncthreads();

    float acc = 0.f;
    #pragma unroll
    for (int i = 0; i < 8; i++) acc = fmaf(vsum[i][tid], wscale[i], acc);
    acc *= s_inv;

    if (final_iter) {
        dout[(size_t)g * 512 + tid] = qs[tid];
        dout[(size_t)g * 512 + 256 + tid] = acc;
    } else {
        __nv_bfloat16 h, l;
        split_bf16(qs[tid], h, l);
        d_X0h[(size_t)g * 768 + tid] = h;
        d_X0l[(size_t)g * 768 + tid] = l;
        split_bf16(acc, h, l);
        d_X0h[(size_t)g * 768 + 256 + tid] = h;
        d_X0l[(size_t)g * 768 + 256 + tid] = l;
    }
}

// ---------------- mma.sync bf16-split GEMM: gates = X * W^T ----
// CTA tile 128x128, 8 warps (4m x 2n), warp tile 32x64, BK=32,
// 3-stage cp.async pipeline with ONE __syncthreads per K-iter.
#define ROWB 80                    // padded row bytes (conflict-free ldmatrix)
#define ARR  (128 * ROWB)          // 10240 B per array
#define STG  (4 * ARR)             // 40960 B per stage
#define SMEM_GEMM (3 * STG)        // 122880 B

__global__ __launch_bounds__(256, 1) void mma_gates(int layer, int B) {
    const __nv_bfloat16* __restrict__ Agh = layer ? d_X1h : d_X0h;
    const __nv_bfloat16* __restrict__ Agl = layer ? d_X1l : d_X0l;
    const __nv_bfloat16* __restrict__ Wgh = layer ? d_W1h : d_W0h;
    const __nv_bfloat16* __restrict__ Wgl = layer ? d_W1l : d_W0l;
    const int K = layer ? 512 : 768;

    extern __shared__ __nv_bfloat16 sm[];
    const uint32_t sbase = smem_u32(sm);

    const int tid = threadIdx.x, lane = tid & 31, warp = tid >> 5;
    const int wm = warp >> 1, wn = warp & 1;
    const int tm = blockIdx.y, tn = blockIdx.x;

    float c[2][8][4];
    #pragma unroll
    for (int i = 0; i < 2; i++)
        #pragma unroll
        for (int j = 0; j < 8; j++)
            #pragma unroll
            for (int k = 0; k < 4; k++) c[i][j][k] = 0.f;

    int idx0 = tid, idx1 = tid + 256;
    int row0 = idx0 >> 2, ch0 = idx0 & 3;
    int row1 = idx1 >> 2, ch1 = idx1 & 3;
    int ar0 = tm * 128 + row0; if (ar0 >= B) ar0 = B - 1;
    int ar1 = tm * 128 + row1; if (ar1 >= B) ar1 = B - 1;
    int br0 = tn * 128 + row0;
    int br1 = tn * 128 + row1;

    const int niter = K >> 5;

    #define ISSUE(I, BUF) do {                                                   \
        int _k0 = (I) << 5;                                                      \
        uint32_t _d0 = sbase + (BUF) * STG + row0 * ROWB + ch0 * 16;             \
        uint32_t _d1 = sbase + (BUF) * STG + row1 * ROWB + ch1 * 16;             \
        size_t _a0 = (size_t)ar0 * K + _k0 + ch0 * 8;                            \
        size_t _a1 = (size_t)ar1 * K + _k0 + ch1 * 8;                            \
        size_t _b0 = (size_t)br0 * K + _k0 + ch0 * 8;                            \
        size_t _b1 = (size_t)br1 * K + _k0 + ch1 * 8;                            \
        cp16(_d0 + 0 * ARR, Agh + _a0);  cp16(_d1 + 0 * ARR, Agh + _a1);         \
        cp16(_d0 + 1 * ARR, Agl + _a0);  cp16(_d1 + 1 * ARR, Agl + _a1);         \
        cp16(_d0 + 2 * ARR, Wgh + _b0);  cp16(_d1 + 2 * ARR, Wgh + _b1);         \
        cp16(_d0 + 3 * ARR, Wgl + _b0);  cp16(_d1 + 3 * ARR, Wgl + _b1);         \
        CP_COMMIT();                                                             \
    } while (0)

    ISSUE(0, 0);
    ISSUE(1, 1);

    const int m0 = wm * 32, n0 = wn * 64;
    const uint32_t a_row = m0 + (lane & 15);
    const uint32_t a_koff = (lane >> 4) * 16;
    const uint32_t b_row = n0 + (lane & 7) + ((lane >> 4) << 3);
    const uint32_t b_koff = ((lane >> 3) & 1) * 16;

    int buf = 0, nbuf = 2;
    for (int i = 0; i < niter; i++) {
        // chunk i and i+1 are in flight; wait for chunk i only
        if (i + 1 < niter) CP_WAIT1(); else CP_WAIT0();
        __syncthreads();
        // buffer nbuf held chunk i-1, fully consumed before the sync above
        if (i + 2 < niter) ISSUE(i + 2, nbuf);

        uint32_t sb = sbase + buf * STG;
        uint32_t aAh = sb + 0 * ARR, aAl = sb + 1 * ARR;
        uint32_t aBh = sb + 2 * ARR, aBl = sb + 3 * ARR;

        #pragma unroll
        for (int kk = 0; kk < 2; kk++) {
            uint32_t kb = kk * 32;
            uint32_t ah[2][4], al[2][4], bh[4][4], bl[4][4];
            ldsm4(ah[0], aAh + a_row * ROWB + kb + a_koff);
            ldsm4(ah[1], aAh + (a_row + 16) * ROWB + kb + a_koff);
            ldsm4(al[0], aAl + a_row * ROWB + kb + a_koff);
            ldsm4(al[1], aAl + (a_row + 16) * ROWB + kb + a_koff);
            #pragma unroll
            for (int nb = 0; nb < 4; nb++) {
                ldsm4(bh[nb], aBh + (b_row + nb * 16) * ROWB + kb + b_koff);
                ldsm4(bl[nb], aBl + (b_row + nb * 16) * ROWB + kb + b_koff);
            }
            #pragma unroll
            for (int mi = 0; mi < 2; mi++)
                #pragma unroll
                for (int nb = 0; nb < 4; nb++)
                    #pragma unroll
                    for (int h = 0; h < 2; h++) {
                        int n8 = nb * 2 + h;
                        mma16816(c[mi][n8], ah[mi], &bh[nb][h * 2]);   // hi*hi
                        mma16816(c[mi][n8], ah[mi], &bl[nb][h * 2]);   // hi*lo
                        mma16816(c[mi][n8], al[mi], &bh[nb][h * 2]);   // lo*hi
                    }
        }
        buf = (buf == 2) ? 0 : buf + 1;
        nbuf = (nbuf == 2) ? 0 : nbuf + 1;
    }

    // epilogue: write fp32 gates
    int g = lane >> 2, qt = lane & 3;
    #pragma unroll
    for (int mi = 0; mi < 2; mi++) {
        #pragma unroll
        for (int n8 = 0; n8 < 8; n8++) {
            int row = tm * 128 + m0 + mi * 16 + g;
            int col = tn * 128 + n0 + n8 * 8 + qt * 2;
            if (row < B)
                *(float2*)&d_gates[(size_t)row * 1024 + col] = make_float2(c[mi][n8][0], c[mi][n8][1]);
            if (row + 8 < B)
                *(float2*)&d_gates[(size_t)(row + 8) * 1024 + col] = make_float2(c[mi][n8][2], c[mi][n8][3]);
        }
    }
    #undef ISSUE
}

// ---------------- LSTM pointwise: gates -> (h, c), writes bf16 split inputs ----
__global__ void lstm_act_kernel(int layer, int B) {
    int idx = blockIdx.x * blockDim.x + threadIdx.x;
    if (idx >= B * 256) return;
    int b = idx >> 8, t = idx & 255;
    const float* gr = d_gates + (size_t)b * 1024;
    const float* bs = (layer == 0) ? d_b0 : d_b1;
    float* c = (layer == 0) ? d_c0 : d_c1;

    float gi = gr[t]       + bs[t];
    float gf = gr[t + 256] + bs[t + 256];
    float gg = gr[t + 512] + bs[t + 512];
    float go = gr[t + 768] + bs[t + 768];

    float si = 1.f / (1.f + expf(-gi));
    float sf = 1.f / (1.f + expf(-gf));
    float tg = tanhf(gg);
    float so = 1.f / (1.f + expf(-go));

    float cn = sf * c[idx] + si * tg;
    c[idx] = cn;
    float hn = so * tanhf(cn);

    __nv_bfloat16 h, l;
    split_bf16(hn, h, l);
    if (layer == 0) {
        d_X0h[(size_t)b * 768 + 512 + t] = h;
        d_X0l[(size_t)b * 768 + 512 + t] = l;
        d_X1h[(size_t)b * 512 + t]       = h;
        d_X1l[(size_t)b * 512 + t]       = l;
    } else {
        d_X1h[(size_t)b * 512 + 256 + t] = h;
        d_X1l[(size_t)b * 512 + 256 + t] = l;
        d_q[idx] = hn;
    }
}

// ---------------- host launcher ----------------
extern "C" void kernel_launch(void* const* d_in, const int* in_sizes, int n_in,
                              void* d_out, int out_size) {
    const float* nodes = (const float*)d_in[0];
    const void*  gid   = d_in[1];
    int N = in_sizes[1];

    int wbase = (in_sizes[2] == 1) ? 3 : 2;
    const float* Wih0 = (const float*)d_in[wbase + 0];
    const float* Whh0 = (const float*)d_in[wbase + 1];
    const float* bih0 = (const float*)d_in[wbase + 2];
    const float* bhh0 = (const float*)d_in[wbase + 3];
    const float* Wih1 = (const float*)d_in[wbase + 4];
    const float* Whh1 = (const float*)d_in[wbase + 5];
    const float* bih1 = (const float*)d_in[wbase + 6];
    const float* bhh1 = (const float*)d_in[wbase + 7];

    int B = out_size / (2 * Hh);
    float* out = (float*)d_out;

    cudaFuncSetAttribute(mma_gates, cudaFuncAttributeMaxDynamicSharedMemorySize, SMEM_GEMM);

    detect_kernel<<<1, 1>>>((const int*)gid, N);
    starts_kernel<<<(B + 1 + 255) / 256, 256>>>(gid, N, B);
    pack_kernel<<<(1024 * 768 + 255) / 256, 256>>>(Wih0, Whh0, bih0, bhh0,
                                                   Wih1, Whh1, bih1, bhh1);
    init_kernel<<<(B * 768 + 255) / 256, 256>>>(B);

    dim3 gemm_grid(1024 / 128, (B + 127) / 128);
    const int M_ITERS = 6;
    for (int i = 0; i < M_ITERS; i++) {
        int final_iter = (i == M_ITERS - 1) ? 1 : 0;
        attention_kernel<<<B, 256>>>(nodes, out, final_iter);
        if (!final_iter) {
            mma_gates<<<gemm_grid, 256, SMEM_GEMM>>>(0, B);
            lstm_act_kernel<<<(B * 256 + 255) / 256, 256>>>(0, B);
            mma_gates<<<gemm_grid, 256, SMEM_GEMM>>>(1, B);
            lstm_act_kernel<<<(B * 256 + 255) / 256, 256>>>(1, B);
        }
    }
}

// round 10
// speedup vs baseline: 1.6807x; 1.1584x over previous
#include <cuda_runtime.h>
#include <cuda_fp16.h>
#include <math.h>
#include <stdint.h>

#define Hh 256
#define NMAX 262144
#define BMAX 4096

// ---------------- device scratch (no allocations allowed) ----------------
__device__ int   d_starts[BMAX + 1];
__device__ int   d_is64;
__device__ float d_q[BMAX * 256];            // q = h1 (fp32, for attention)
__device__ float d_gates[BMAX * 1024];
__device__ float d_c0[BMAX * 256];
__device__ float d_c1[BMAX * 256];
// fp16 split X (hi+lo), fp16 single W
__device__ __half d_X0h[BMAX * 768], d_X0l[BMAX * 768];   // [q_star(512)|h0(256)]
__device__ __half d_X1h[BMAX * 512], d_X1l[BMAX * 512];   // [h0(256)|h1(256)]
__device__ __half d_W0[1024 * 768];                        // [Wih0|Whh0]
__device__ __half d_W1[1024 * 512];                        // [Wih1|Whh1]
__device__ float d_b0[1024], d_b1[1024];

// ---------------- small helpers ----------------
__device__ __forceinline__ uint32_t smem_u32(const void* p) {
    uint32_t a;
    asm("{ .reg .u64 t; cvta.to.shared.u64 t, %1; cvt.u32.u64 %0, t; }" : "=r"(a) : "l"(p));
    return a;
}
__device__ __forceinline__ void cp16(uint32_t dst, const void* src) {
    asm volatile("cp.async.cg.shared.global [%0], [%1], 16;" :: "r"(dst), "l"(src));
}
#define CP_COMMIT() asm volatile("cp.async.commit_group;" ::: "memory")
#define CP_WAIT1()  asm volatile("cp.async.wait_group 1;" ::: "memory")
#define CP_WAIT0()  asm volatile("cp.async.wait_group 0;" ::: "memory")

__device__ __forceinline__ void ldsm4(uint32_t* r, uint32_t addr) {
    asm volatile("ldmatrix.sync.aligned.m8n8.x4.shared.b16 {%0,%1,%2,%3}, [%4];"
                 : "=r"(r[0]), "=r"(r[1]), "=r"(r[2]), "=r"(r[3]) : "r"(addr));
}
__device__ __forceinline__ void mma16816(float* c, const uint32_t* a, const uint32_t* b) {
    asm volatile(
        "mma.sync.aligned.m16n8k16.row.col.f32.f16.f16.f32 "
        "{%0,%1,%2,%3},{%4,%5,%6,%7},{%8,%9},{%0,%1,%2,%3};"
        : "+f"(c[0]), "+f"(c[1]), "+f"(c[2]), "+f"(c[3])
        : "r"(a[0]), "r"(a[1]), "r"(a[2]), "r"(a[3]), "r"(b[0]), "r"(b[1]));
}
__device__ __forceinline__ void split_fp16(float x, __half& h, __half& l) {
    h = __float2half_rn(x);
    l = __float2half_rn(x - __half2float(h));
}

// ---------------- graph_id dtype detection ----------------
__global__ void detect_kernel(const int* p, int N) {
    int z = 1;
    for (int j = 0; j < 8; j++) {
        int idx = N - 1 - 2 * j;
        if (idx < 1) break;
        if ((idx & 1) == 0) idx--;
        if (idx >= 1 && p[idx] != 0) z = 0;
    }
    d_is64 = z;
}
__device__ __forceinline__ int get_gid(const void* p, int i) {
    if (d_is64) return (int)((const long long*)p)[i];
    return ((const int*)p)[i];
}
__global__ void starts_kernel(const void* gid, int N, int B) {
    int g = blockIdx.x * blockDim.x + threadIdx.x;
    if (g > B) return;
    int lo = 0, hi = N;
    while (lo < hi) {
        int mid = (lo + hi) >> 1;
        if (get_gid(gid, mid) < g) lo = mid + 1; else hi = mid;
    }
    d_starts[g] = lo;
}

// ---------------- pack weights (fp16) + summed biases ----------------
__global__ void pack_kernel(const float* __restrict__ Wih0, const float* __restrict__ Whh0,
                            const float* __restrict__ bih0, const float* __restrict__ bhh0,
                            const float* __restrict__ Wih1, const float* __restrict__ Whh1,
                            const float* __restrict__ bih1, const float* __restrict__ bhh1) {
    int i = blockIdx.x * blockDim.x + threadIdx.x;
    if (i < 1024 * 768) {
        int j = i / 768, k = i % 768;
        float v = (k < 512) ? Wih0[j * 512 + k] : Whh0[j * 256 + (k - 512)];
        d_W0[i] = __float2half_rn(v);
    }
    if (i < 1024 * 512) {
        int j = i / 512, k = i % 512;
        float v = (k < 256) ? Wih1[j * 256 + k] : Whh1[j * 256 + (k - 256)];
        d_W1[i] = __float2half_rn(v);
    }
    if (i < 1024) {
        d_b0[i] = bih0[i] + bhh0[i];
        d_b1[i] = bih1[i] + bhh1[i];
    }
}

// ---------------- zero-init state ----------------
__global__ void init_kernel(int B) {
    int i = blockIdx.x * blockDim.x + threadIdx.x;
    __half z = __float2half_rn(0.f);
    if (i < B * 768) { d_X0h[i] = z; d_X0l[i] = z; }
    if (i < B * 512) { d_X1h[i] = z; d_X1l[i] = z; }
    if (i < B * 256) { d_c0[i] = 0.f; d_c1[i] = 0.f; d_q[i] = 0.f; }
}

// ---------------- attention: single-pass online softmax (float4 loads) ----------------
__global__ void attention_kernel(const float* __restrict__ nodes,
                                 float* __restrict__ dout, int final_iter) {
    int g = blockIdx.x;
    int s = d_starts[g], en = d_starts[g + 1];
    __shared__ float qs[256];
    __shared__ float vsum[8][256];
    __shared__ float wm[8], ws[8], wscale[8];
    __shared__ float s_inv;
    int tid = threadIdx.x, lane = tid & 31, w = tid >> 5;

    qs[tid] = d_q[(size_t)g * 256 + tid];
    __syncthreads();

    float4 q0 = ((const float4*)qs)[lane];
    float4 q1 = ((const float4*)qs)[32 + lane];

    float m = -3.4e38f, ssum = 0.f;
    float4 v0 = make_float4(0.f, 0.f, 0.f, 0.f);
    float4 v1 = make_float4(0.f, 0.f, 0.f, 0.f);

    for (int n = s + w; n < en; n += 8) {
        const float4* row4 = (const float4*)(nodes + (size_t)n * 256);
        float4 x0 = row4[lane];
        float4 x1 = row4[32 + lane];
        float d = x0.x * q0.x + x0.y * q0.y + x0.z * q0.z + x0.w * q0.w
                + x1.x * q1.x + x1.y * q1.y + x1.z * q1.z + x1.w * q1.w;
        #pragma unroll
        for (int o = 16; o; o >>= 1) d += __shfl_xor_sync(0xffffffffu, d, o);

        float mn = fmaxf(m, d);
        float scale = __expf(m - mn);    // 0 on first row (m=-inf)
        float e = __expf(d - mn);
        ssum = ssum * scale + e;
        v0.x = fmaf(v0.x, scale, e * x0.x); v0.y = fmaf(v0.y, scale, e * x0.y);
        v0.z = fmaf(v0.z, scale, e * x0.z); v0.w = fmaf(v0.w, scale, e * x0.w);
        v1.x = fmaf(v1.x, scale, e * x1.x); v1.y = fmaf(v1.y, scale, e * x1.y);
        v1.z = fmaf(v1.z, scale, e * x1.z); v1.w = fmaf(v1.w, scale, e * x1.w);
        m = mn;
    }

    if (lane == 0) { wm[w] = m; ws[w] = ssum; }
    ((float4*)vsum[w])[lane] = v0;
    ((float4*)vsum[w])[32 + lane] = v1;
    __syncthreads();

    if (tid == 0) {
        float M = -3.4e38f;
        #pragma unroll
        for (int i = 0; i < 8; i++) if (ws[i] > 0.f) M = fmaxf(M, wm[i]);
        float S = 0.f;
        #pragma unroll
        for (int i = 0; i < 8; i++) {
            float sc = (ws[i] > 0.f) ? __expf(wm[i] - M) : 0.f;
            wscale[i] = sc;
            S += ws[i] * sc;
        }
        s_inv = (S > 0.f) ? 1.f / S : 0.f;
    }
    __syncthreads();

    float acc = 0.f;
    #pragma unroll
    for (int i = 0; i < 8; i++) acc = fmaf(vsum[i][tid], wscale[i], acc);
    acc *= s_inv;

    if (final_iter) {
        dout[(size_t)g * 512 + tid] = qs[tid];
        dout[(size_t)g * 512 + 256 + tid] = acc;
    } else {
        __half h, l;
        split_fp16(qs[tid], h, l);
        d_X0h[(size_t)g * 768 + tid] = h;
        d_X0l[(size_t)g * 768 + tid] = l;
        split_fp16(acc, h, l);
        d_X0h[(size_t)g * 768 + 256 + tid] = h;
        d_X0l[(size_t)g * 768 + 256 + tid] = l;
    }
}

// ---------------- mma.sync fp16 2-product GEMM: gates = X * W^T ----
// D = (Ah + Al) * W, W fp16 single. CTA tile 128x128, 8 warps (4m x 2n),
// warp tile 32x64, BK=32, 3-stage cp.async, one sync per K-iter.
#define ROWB 80                    // padded row bytes (conflict-free ldmatrix)
#define ARR  (128 * ROWB)          // 10240 B per array
#define STG  (3 * ARR)             // 30720 B per stage (Ah, Al, B)
#define SMEM_GEMM (3 * STG)        // 92160 B

__global__ __launch_bounds__(256, 1) void mma_gates(int layer, int B) {
    const __half* __restrict__ Agh = layer ? d_X1h : d_X0h;
    const __half* __restrict__ Agl = layer ? d_X1l : d_X0l;
    const __half* __restrict__ Wg  = layer ? d_W1  : d_W0;
    const int K = layer ? 512 : 768;

    extern __shared__ __half sm[];
    const uint32_t sbase = smem_u32(sm);

    const int tid = threadIdx.x, lane = tid & 31, warp = tid >> 5;
    const int wm = warp >> 1, wn = warp & 1;
    const int tm = blockIdx.y, tn = blockIdx.x;

    float c[2][8][4];
    #pragma unroll
    for (int i = 0; i < 2; i++)
        #pragma unroll
        for (int j = 0; j < 8; j++)
            #pragma unroll
            for (int k = 0; k < 4; k++) c[i][j][k] = 0.f;

    int idx0 = tid, idx1 = tid + 256;
    int row0 = idx0 >> 2, ch0 = idx0 & 3;
    int row1 = idx1 >> 2, ch1 = idx1 & 3;
    int ar0 = tm * 128 + row0; if (ar0 >= B) ar0 = B - 1;
    int ar1 = tm * 128 + row1; if (ar1 >= B) ar1 = B - 1;
    int br0 = tn * 128 + row0;
    int br1 = tn * 128 + row1;

    const int niter = K >> 5;

    #define ISSUE(I, BUF) do {                                                   \
        int _k0 = (I) << 5;                                                      \
        uint32_t _d0 = sbase + (BUF) * STG + row0 * ROWB + ch0 * 16;             \
        uint32_t _d1 = sbase + (BUF) * STG + row1 * ROWB + ch1 * 16;             \
        size_t _a0 = (size_t)ar0 * K + _k0 + ch0 * 8;                            \
        size_t _a1 = (size_t)ar1 * K + _k0 + ch1 * 8;                            \
        size_t _b0 = (size_t)br0 * K + _k0 + ch0 * 8;                            \
        size_t _b1 = (size_t)br1 * K + _k0 + ch1 * 8;                            \
        cp16(_d0 + 0 * ARR, Agh + _a0);  cp16(_d1 + 0 * ARR, Agh + _a1);         \
        cp16(_d0 + 1 * ARR, Agl + _a0);  cp16(_d1 + 1 * ARR, Agl + _a1);         \
        cp16(_d0 + 2 * ARR, Wg  + _b0);  cp16(_d1 + 2 * ARR, Wg  + _b1);         \
        CP_COMMIT();                                                             \
    } while (0)

    ISSUE(0, 0);
    ISSUE(1, 1);

    const int m0 = wm * 32, n0 = wn * 64;
    const uint32_t a_row = m0 + (lane & 15);
    const uint32_t a_koff = (lane >> 4) * 16;
    const uint32_t b_row = n0 + (lane & 7) + ((lane >> 4) << 3);
    const uint32_t b_koff = ((lane >> 3) & 1) * 16;

    int buf = 0, nbuf = 2;
    for (int i = 0; i < niter; i++) {
        if (i + 1 < niter) CP_WAIT1(); else CP_WAIT0();
        __syncthreads();
        if (i + 2 < niter) ISSUE(i + 2, nbuf);

        uint32_t sb = sbase + buf * STG;
        uint32_t aAh = sb + 0 * ARR, aAl = sb + 1 * ARR;
        uint32_t aB  = sb + 2 * ARR;

        #pragma unroll
        for (int kk = 0; kk < 2; kk++) {
            uint32_t kb = kk * 32;
            uint32_t ah[2][4], al[2][4], bh[4][4];
            ldsm4(ah[0], aAh + a_row * ROWB + kb + a_koff);
            ldsm4(ah[1], aAh + (a_row + 16) * ROWB + kb + a_koff);
            ldsm4(al[0], aAl + a_row * ROWB + kb + a_koff);
            ldsm4(al[1], aAl + (a_row + 16) * ROWB + kb + a_koff);
            #pragma unroll
            for (int nb = 0; nb < 4; nb++)
                ldsm4(bh[nb], aB + (b_row + nb * 16) * ROWB + kb + b_koff);
            #pragma unroll
            for (int mi = 0; mi < 2; mi++)
                #pragma unroll
                for (int nb = 0; nb < 4; nb++)
                    #pragma unroll
                    for (int h = 0; h < 2; h++) {
                        int n8 = nb * 2 + h;
                        mma16816(c[mi][n8], ah[mi], &bh[nb][h * 2]);   // Ah*W
                        mma16816(c[mi][n8], al[mi], &bh[nb][h * 2]);   // Al*W
                    }
        }
        buf = (buf == 2) ? 0 : buf + 1;
        nbuf = (nbuf == 2) ? 0 : nbuf + 1;
    }

    // epilogue: write fp32 gates
    int g = lane >> 2, qt = lane & 3;
    #pragma unroll
    for (int mi = 0; mi < 2; mi++) {
        #pragma unroll
        for (int n8 = 0; n8 < 8; n8++) {
            int row = tm * 128 + m0 + mi * 16 + g;
            int col = tn * 128 + n0 + n8 * 8 + qt * 2;
            if (row < B)
                *(float2*)&d_gates[(size_t)row * 1024 + col] = make_float2(c[mi][n8][0], c[mi][n8][1]);
            if (row + 8 < B)
                *(float2*)&d_gates[(size_t)(row + 8) * 1024 + col] = make_float2(c[mi][n8][2], c[mi][n8][3]);
        }
    }
    #undef ISSUE
}

// ---------------- LSTM pointwise: gates -> (h, c), writes fp16 split inputs ----
__global__ void lstm_act_kernel(int layer, int B) {
    int idx = blockIdx.x * blockDim.x + threadIdx.x;
    if (idx >= B * 256) return;
    int b = idx >> 8, t = idx & 255;
    const float* gr = d_gates + (size_t)b * 1024;
    const float* bs = (layer == 0) ? d_b0 : d_b1;
    float* c = (layer == 0) ? d_c0 : d_c1;

    float gi = gr[t]       + bs[t];
    float gf = gr[t + 256] + bs[t + 256];
    float gg = gr[t + 512] + bs[t + 512];
    float go = gr[t + 768] + bs[t + 768];

    float si = 1.f / (1.f + expf(-gi));
    float sf = 1.f / (1.f + expf(-gf));
    float tg = tanhf(gg);
    float so = 1.f / (1.f + expf(-go));

    float cn = sf * c[idx] + si * tg;
    c[idx] = cn;
    float hn = so * tanhf(cn);

    __half h, l;
    split_fp16(hn, h, l);
    if (layer == 0) {
        d_X0h[(size_t)b * 768 + 512 + t] = h;
        d_X0l[(size_t)b * 768 + 512 + t] = l;
        d_X1h[(size_t)b * 512 + t]       = h;
        d_X1l[(size_t)b * 512 + t]       = l;
    } else {
        d_X1h[(size_t)b * 512 + 256 + t] = h;
        d_X1l[(size_t)b * 512 + 256 + t] = l;
        d_q[idx] = hn;
    }
}

// ---------------- host launcher ----------------
extern "C" void kernel_launch(void* const* d_in, const int* in_sizes, int n_in,
                              void* d_out, int out_size) {
    const float* nodes = (const float*)d_in[0];
    const void*  gid   = d_in[1];
    int N = in_sizes[1];

    int wbase = (in_sizes[2] == 1) ? 3 : 2;
    const float* Wih0 = (const float*)d_in[wbase + 0];
    const float* Whh0 = (const float*)d_in[wbase + 1];
    const float* bih0 = (const float*)d_in[wbase + 2];
    const float* bhh0 = (const float*)d_in[wbase + 3];
    const float* Wih1 = (const float*)d_in[wbase + 4];
    const float* Whh1 = (const float*)d_in[wbase + 5];
    const float* bih1 = (const float*)d_in[wbase + 6];
    const float* bhh1 = (const float*)d_in[wbase + 7];

    int B = out_size / (2 * Hh);
    float* out = (float*)d_out;

    cudaFuncSetAttribute(mma_gates, cudaFuncAttributeMaxDynamicSharedMemorySize, SMEM_GEMM);

    detect_kernel<<<1, 1>>>((const int*)gid, N);
    starts_kernel<<<(B + 1 + 255) / 256, 256>>>(gid, N, B);
    pack_kernel<<<(1024 * 768 + 255) / 256, 256>>>(Wih0, Whh0, bih0, bhh0,
                                                   Wih1, Whh1, bih1, bhh1);
    init_kernel<<<(B * 768 + 255) / 256, 256>>>(B);

    dim3 gemm_grid(1024 / 128, (B + 127) / 128);
    const int M_ITERS = 6;
    for (int i = 0; i < M_ITERS; i++) {
        int final_iter = (i == M_ITERS - 1) ? 1 : 0;
        attention_kernel<<<B, 256>>>(nodes, out, final_iter);
        if (!final_iter) {
            mma_gates<<<gemm_grid, 256, SMEM_GEMM>>>(0, B);
            lstm_act_kernel<<<(B * 256 + 255) / 256, 256>>>(0, B);
            mma_gates<<<gemm_grid, 256, SMEM_GEMM>>>(1, B);
            lstm_act_kernel<<<(B * 256 + 255) / 256, 256>>>(1, B);
        }
    }
}

// round 11
// speedup vs baseline: 1.9299x; 1.1483x over previous
#include <cuda_runtime.h>
#include <cuda_fp16.h>
#include <math.h>
#include <stdint.h>

#define Hh 256
#define NMAX 262144
#define BMAX 4096

// ---------------- device scratch (no allocations allowed) ----------------
__device__ int   d_starts[BMAX + 1];
__device__ int   d_is64;
__device__ float d_q[BMAX * 256];            // q = h1 (fp32, for attention)
__device__ float d_gates[BMAX * 1024];
__device__ float d_c0[BMAX * 256];
__device__ float d_c1[BMAX * 256];
// fp16 operands
__device__ __half d_X0[BMAX * 768];          // [q_star(512)|h0(256)]
__device__ __half d_X1[BMAX * 512];          // [h0(256)|h1(256)]
__device__ __half d_W0[1024 * 768];          // [Wih0|Whh0]
__device__ __half d_W1[1024 * 512];          // [Wih1|Whh1]
__device__ float d_b0[1024], d_b1[1024];

// ---------------- small helpers ----------------
__device__ __forceinline__ uint32_t smem_u32(const void* p) {
    uint32_t a;
    asm("{ .reg .u64 t; cvta.to.shared.u64 t, %1; cvt.u32.u64 %0, t; }" : "=r"(a) : "l"(p));
    return a;
}
__device__ __forceinline__ void cp16(uint32_t dst, const void* src) {
    asm volatile("cp.async.cg.shared.global [%0], [%1], 16;" :: "r"(dst), "l"(src));
}
#define CP_COMMIT() asm volatile("cp.async.commit_group;" ::: "memory")
#define CP_WAIT1()  asm volatile("cp.async.wait_group 1;" ::: "memory")
#define CP_WAIT0()  asm volatile("cp.async.wait_group 0;" ::: "memory")

__device__ __forceinline__ void ldsm4(uint32_t* r, uint32_t addr) {
    asm volatile("ldmatrix.sync.aligned.m8n8.x4.shared.b16 {%0,%1,%2,%3}, [%4];"
                 : "=r"(r[0]), "=r"(r[1]), "=r"(r[2]), "=r"(r[3]) : "r"(addr));
}
__device__ __forceinline__ void mma16816(float* c, const uint32_t* a, const uint32_t* b) {
    asm volatile(
        "mma.sync.aligned.m16n8k16.row.col.f32.f16.f16.f32 "
        "{%0,%1,%2,%3},{%4,%5,%6,%7},{%8,%9},{%0,%1,%2,%3};"
        : "+f"(c[0]), "+f"(c[1]), "+f"(c[2]), "+f"(c[3])
        : "r"(a[0]), "r"(a[1]), "r"(a[2]), "r"(a[3]), "r"(b[0]), "r"(b[1]));
}

// ---------------- graph_id dtype detection ----------------
__global__ void detect_kernel(const int* p, int N) {
    int z = 1;
    for (int j = 0; j < 8; j++) {
        int idx = N - 1 - 2 * j;
        if (idx < 1) break;
        if ((idx & 1) == 0) idx--;
        if (idx >= 1 && p[idx] != 0) z = 0;
    }
    d_is64 = z;
}
__device__ __forceinline__ int get_gid(const void* p, int i) {
    if (d_is64) return (int)((const long long*)p)[i];
    return ((const int*)p)[i];
}
__global__ void starts_kernel(const void* gid, int N, int B) {
    int g = blockIdx.x * blockDim.x + threadIdx.x;
    if (g > B) return;
    int lo = 0, hi = N;
    while (lo < hi) {
        int mid = (lo + hi) >> 1;
        if (get_gid(gid, mid) < g) lo = mid + 1; else hi = mid;
    }
    d_starts[g] = lo;
}

// ---------------- pack weights (fp16) + summed biases ----------------
__global__ void pack_kernel(const float* __restrict__ Wih0, const float* __restrict__ Whh0,
                            const float* __restrict__ bih0, const float* __restrict__ bhh0,
                            const float* __restrict__ Wih1, const float* __restrict__ Whh1,
                            const float* __restrict__ bih1, const float* __restrict__ bhh1) {
    int i = blockIdx.x * blockDim.x + threadIdx.x;
    if (i < 1024 * 768) {
        int j = i / 768, k = i % 768;
        float v = (k < 512) ? Wih0[j * 512 + k] : Whh0[j * 256 + (k - 512)];
        d_W0[i] = __float2half_rn(v);
    }
    if (i < 1024 * 512) {
        int j = i / 512, k = i % 512;
        float v = (k < 256) ? Wih1[j * 256 + k] : Whh1[j * 256 + (k - 256)];
        d_W1[i] = __float2half_rn(v);
    }
    if (i < 1024) {
        d_b0[i] = bih0[i] + bhh0[i];
        d_b1[i] = bih1[i] + bhh1[i];
    }
}

// ---------------- zero-init state ----------------
__global__ void init_kernel(int B) {
    int i = blockIdx.x * blockDim.x + threadIdx.x;
    __half z = __float2half_rn(0.f);
    if (i < B * 768) d_X0[i] = z;
    if (i < B * 512) d_X1[i] = z;
    if (i < B * 256) { d_c0[i] = 0.f; d_c1[i] = 0.f; d_q[i] = 0.f; }
}

// ---------------- attention: single-pass online softmax (float4 loads) ----------------
__global__ void attention_kernel(const float* __restrict__ nodes,
                                 float* __restrict__ dout, int final_iter) {
    int g = blockIdx.x;
    int s = d_starts[g], en = d_starts[g + 1];
    __shared__ float qs[256];
    __shared__ float vsum[8][256];
    __shared__ float wm[8], ws[8], wscale[8];
    __shared__ float s_inv;
    int tid = threadIdx.x, lane = tid & 31, w = tid >> 5;

    qs[tid] = d_q[(size_t)g * 256 + tid];
    __syncthreads();

    float4 q0 = ((const float4*)qs)[lane];
    float4 q1 = ((const float4*)qs)[32 + lane];

    float m = -3.4e38f, ssum = 0.f;
    float4 v0 = make_float4(0.f, 0.f, 0.f, 0.f);
    float4 v1 = make_float4(0.f, 0.f, 0.f, 0.f);

    for (int n = s + w; n < en; n += 8) {
        const float4* row4 = (const float4*)(nodes + (size_t)n * 256);
        float4 x0 = row4[lane];
        float4 x1 = row4[32 + lane];
        float d = x0.x * q0.x + x0.y * q0.y + x0.z * q0.z + x0.w * q0.w
                + x1.x * q1.x + x1.y * q1.y + x1.z * q1.z + x1.w * q1.w;
        #pragma unroll
        for (int o = 16; o; o >>= 1) d += __shfl_xor_sync(0xffffffffu, d, o);

        float mn = fmaxf(m, d);
        float scale = __expf(m - mn);    // 0 on first row (m=-inf)
        float e = __expf(d - mn);
        ssum = ssum * scale + e;
        v0.x = fmaf(v0.x, scale, e * x0.x); v0.y = fmaf(v0.y, scale, e * x0.y);
        v0.z = fmaf(v0.z, scale, e * x0.z); v0.w = fmaf(v0.w, scale, e * x0.w);
        v1.x = fmaf(v1.x, scale, e * x1.x); v1.y = fmaf(v1.y, scale, e * x1.y);
        v1.z = fmaf(v1.z, scale, e * x1.z); v1.w = fmaf(v1.w, scale, e * x1.w);
        m = mn;
    }

    if (lane == 0) { wm[w] = m; ws[w] = ssum; }
    ((float4*)vsum[w])[lane] = v0;
    ((float4*)vsum[w])[32 + lane] = v1;
    __syncthreads();

    if (tid == 0) {
        float M = -3.4e38f;
        #pragma unroll
        for (int i = 0; i < 8; i++) if (ws[i] > 0.f) M = fmaxf(M, wm[i]);
        float S = 0.f;
        #pragma unroll
        for (int i = 0; i < 8; i++) {
            float sc = (ws[i] > 0.f) ? __expf(wm[i] - M) : 0.f;
            wscale[i] = sc;
            S += ws[i] * sc;
        }
        s_inv = (S > 0.f) ? 1.f / S : 0.f;
    }
    __syncthreads();

    float acc = 0.f;
    #pragma unroll
    for (int i = 0; i < 8; i++) acc = fmaf(vsum[i][tid], wscale[i], acc);
    acc *= s_inv;

    if (final_iter) {
        dout[(size_t)g * 512 + tid] = qs[tid];
        dout[(size_t)g * 512 + 256 + tid] = acc;
    } else {
        d_X0[(size_t)g * 768 + tid] = __float2half_rn(qs[tid]);
        d_X0[(size_t)g * 768 + 256 + tid] = __float2half_rn(acc);
    }
}

// ---------------- mma.sync fp16 GEMM: gates = X * W^T ----
// CTA tile 128x128, 8 warps (4m x 2n), warp tile 32x64, BK=32,
// 3-stage cp.async, one sync per K-iter.
#define ROWB 80                    // padded row bytes (conflict-free ldmatrix)
#define ARR  (128 * ROWB)          // 10240 B per array
#define STG  (2 * ARR)             // 20480 B per stage (A, B)
#define SMEM_GEMM (3 * STG)        // 61440 B

__global__ __launch_bounds__(256, 1) void mma_gates(int layer, int B) {
    const __half* __restrict__ Ag = layer ? d_X1 : d_X0;
    const __half* __restrict__ Wg = layer ? d_W1 : d_W0;
    const int K = layer ? 512 : 768;

    extern __shared__ __half sm[];
    const uint32_t sbase = smem_u32(sm);

    const int tid = threadIdx.x, lane = tid & 31, warp = tid >> 5;
    const int wm = warp >> 1, wn = warp & 1;
    const int tm = blockIdx.y, tn = blockIdx.x;

    float c[2][8][4];
    #pragma unroll
    for (int i = 0; i < 2; i++)
        #pragma unroll
        for (int j = 0; j < 8; j++)
            #pragma unroll
            for (int k = 0; k < 4; k++) c[i][j][k] = 0.f;

    int idx0 = tid, idx1 = tid + 256;
    int row0 = idx0 >> 2, ch0 = idx0 & 3;
    int row1 = idx1 >> 2, ch1 = idx1 & 3;
    int ar0 = tm * 128 + row0; if (ar0 >= B) ar0 = B - 1;
    int ar1 = tm * 128 + row1; if (ar1 >= B) ar1 = B - 1;
    int br0 = tn * 128 + row0;
    int br1 = tn * 128 + row1;

    const int niter = K >> 5;

    #define ISSUE(I, BUF) do {                                                   \
        int _k0 = (I) << 5;                                                      \
        uint32_t _d0 = sbase + (BUF) * STG + row0 * ROWB + ch0 * 16;             \
        uint32_t _d1 = sbase + (BUF) * STG + row1 * ROWB + ch1 * 16;             \
        size_t _a0 = (size_t)ar0 * K + _k0 + ch0 * 8;                            \
        size_t _a1 = (size_t)ar1 * K + _k0 + ch1 * 8;                            \
        size_t _b0 = (size_t)br0 * K + _k0 + ch0 * 8;                            \
        size_t _b1 = (size_t)br1 * K + _k0 + ch1 * 8;                            \
        cp16(_d0 + 0 * ARR, Ag + _a0);  cp16(_d1 + 0 * ARR, Ag + _a1);           \
        cp16(_d0 + 1 * ARR, Wg + _b0);  cp16(_d1 + 1 * ARR, Wg + _b1);           \
        CP_COMMIT();                                                             \
    } while (0)

    ISSUE(0, 0);
    ISSUE(1, 1);

    const int m0 = wm * 32, n0 = wn * 64;
    const uint32_t a_row = m0 + (lane & 15);
    const uint32_t a_koff = (lane >> 4) * 16;
    const uint32_t b_row = n0 + (lane & 7) + ((lane >> 4) << 3);
    const uint32_t b_koff = ((lane >> 3) & 1) * 16;

    int buf = 0, nbuf = 2;
    for (int i = 0; i < niter; i++) {
        if (i + 1 < niter) CP_WAIT1(); else CP_WAIT0();
        __syncthreads();
        if (i + 2 < niter) ISSUE(i + 2, nbuf);

        uint32_t sb = sbase + buf * STG;
        uint32_t aA = sb + 0 * ARR;
        uint32_t aB = sb + 1 * ARR;

        #pragma unroll
        for (int kk = 0; kk < 2; kk++) {
            uint32_t kb = kk * 32;
            uint32_t ah[2][4], bh[4][4];
            ldsm4(ah[0], aA + a_row * ROWB + kb + a_koff);
            ldsm4(ah[1], aA + (a_row + 16) * ROWB + kb + a_koff);
            #pragma unroll
            for (int nb = 0; nb < 4; nb++)
                ldsm4(bh[nb], aB + (b_row + nb * 16) * ROWB + kb + b_koff);
            #pragma unroll
            for (int mi = 0; mi < 2; mi++)
                #pragma unroll
                for (int nb = 0; nb < 4; nb++)
                    #pragma unroll
                    for (int h = 0; h < 2; h++) {
                        int n8 = nb * 2 + h;
                        mma16816(c[mi][n8], ah[mi], &bh[nb][h * 2]);
                    }
        }
        buf = (buf == 2) ? 0 : buf + 1;
        nbuf = (nbuf == 2) ? 0 : nbuf + 1;
    }

    // epilogue: write fp32 gates
    int g = lane >> 2, qt = lane & 3;
    #pragma unroll
    for (int mi = 0; mi < 2; mi++) {
        #pragma unroll
        for (int n8 = 0; n8 < 8; n8++) {
            int row = tm * 128 + m0 + mi * 16 + g;
            int col = tn * 128 + n0 + n8 * 8 + qt * 2;
            if (row < B)
                *(float2*)&d_gates[(size_t)row * 1024 + col] = make_float2(c[mi][n8][0], c[mi][n8][1]);
            if (row + 8 < B)
                *(float2*)&d_gates[(size_t)(row + 8) * 1024 + col] = make_float2(c[mi][n8][2], c[mi][n8][3]);
        }
    }
    #undef ISSUE
}

// ---------------- LSTM pointwise: gates -> (h, c), writes fp16 inputs ----
__global__ void lstm_act_kernel(int layer, int B) {
    int idx = blockIdx.x * blockDim.x + threadIdx.x;
    if (idx >= B * 256) return;
    int b = idx >> 8, t = idx & 255;
    const float* gr = d_gates + (size_t)b * 1024;
    const float* bs = (layer == 0) ? d_b0 : d_b1;
    float* c = (layer == 0) ? d_c0 : d_c1;

    float gi = gr[t]       + bs[t];
    float gf = gr[t + 256] + bs[t + 256];
    float gg = gr[t + 512] + bs[t + 512];
    float go = gr[t + 768] + bs[t + 768];

    float si = 1.f / (1.f + expf(-gi));
    float sf = 1.f / (1.f + expf(-gf));
    float tg = tanhf(gg);
    float so = 1.f / (1.f + expf(-go));

    float cn = sf * c[idx] + si * tg;
    c[idx] = cn;
    float hn = so * tanhf(cn);

    __half h = __float2half_rn(hn);
    if (layer == 0) {
        d_X0[(size_t)b * 768 + 512 + t] = h;
        d_X1[(size_t)b * 512 + t]       = h;
    } else {
        d_X1[(size_t)b * 512 + 256 + t] = h;
        d_q[idx] = hn;
    }
}

// ---------------- host launcher ----------------
extern "C" void kernel_launch(void* const* d_in, const int* in_sizes, int n_in,
                              void* d_out, int out_size) {
    const float* nodes = (const float*)d_in[0];
    const void*  gid   = d_in[1];
    int N = in_sizes[1];

    int wbase = (in_sizes[2] == 1) ? 3 : 2;
    const float* Wih0 = (const float*)d_in[wbase + 0];
    const float* Whh0 = (const float*)d_in[wbase + 1];
    const float* bih0 = (const float*)d_in[wbase + 2];
    const float* bhh0 = (const float*)d_in[wbase + 3];
    const float* Wih1 = (const float*)d_in[wbase + 4];
    const float* Whh1 = (const float*)d_in[wbase + 5];
    const float* bih1 = (const float*)d_in[wbase + 6];
    const float* bhh1 = (const float*)d_in[wbase + 7];

    int B = out_size / (2 * Hh);
    float* out = (float*)d_out;

    cudaFuncSetAttribute(mma_gates, cudaFuncAttributeMaxDynamicSharedMemorySize, SMEM_GEMM);

    detect_kernel<<<1, 1>>>((const int*)gid, N);
    starts_kernel<<<(B + 1 + 255) / 256, 256>>>(gid, N, B);
    pack_kernel<<<(1024 * 768 + 255) / 256, 256>>>(Wih0, Whh0, bih0, bhh0,
                                                   Wih1, Whh1, bih1, bhh1);
    init_kernel<<<(B * 768 + 255) / 256, 256>>>(B);

    dim3 gemm_grid(1024 / 128, (B + 127) / 128);
    const int M_ITERS = 6;
    for (int i = 0; i < M_ITERS; i++) {
        int final_iter = (i == M_ITERS - 1) ? 1 : 0;
        attention_kernel<<<B, 256>>>(nodes, out, final_iter);
        if (!final_iter) {
            mma_gates<<<gemm_grid, 256, SMEM_GEMM>>>(0, B);
            lstm_act_kernel<<<(B * 256 + 255) / 256, 256>>>(0, B);
            mma_gates<<<gemm_grid, 256, SMEM_GEMM>>>(1, B);
            lstm_act_kernel<<<(B * 256 + 255) / 256, 256>>>(1, B);
        }
    }
}

// round 12
// speedup vs baseline: 1.9307x; 1.0004x over previous
#include <cuda_runtime.h>
#include <cuda_fp16.h>
#include <math.h>
#include <stdint.h>

#define Hh 256
#define NMAX 262144
#define BMAX 4096

// ---------------- device scratch (no allocations allowed) ----------------
__device__ int    d_starts[BMAX + 1];
__device__ int    d_is64;
__device__ float  d_q[BMAX * 256];           // q = h1 (fp32, for attention)
__device__ float  d_gates[BMAX * 1024];
__device__ float  d_c0[BMAX * 256];
__device__ float  d_c1[BMAX * 256];
__device__ __half d_nodesh[(size_t)NMAX * 256];   // fp16 copy of nodes
// fp16 operands
__device__ __half d_X0[BMAX * 768];          // [q_star(512)|h0(256)]
__device__ __half d_X1[BMAX * 512];          // [h0(256)|h1(256)]
__device__ __half d_W0[1024 * 768];          // [Wih0|Whh0]
__device__ __half d_W1[1024 * 512];          // [Wih1|Whh1]
__device__ float  d_b0[1024], d_b1[1024];

// ---------------- small helpers ----------------
__device__ __forceinline__ uint32_t smem_u32(const void* p) {
    uint32_t a;
    asm("{ .reg .u64 t; cvta.to.shared.u64 t, %1; cvt.u32.u64 %0, t; }" : "=r"(a) : "l"(p));
    return a;
}
__device__ __forceinline__ void cp16(uint32_t dst, const void* src) {
    asm volatile("cp.async.cg.shared.global [%0], [%1], 16;" :: "r"(dst), "l"(src));
}
#define CP_COMMIT() asm volatile("cp.async.commit_group;" ::: "memory")
#define CP_WAIT1()  asm volatile("cp.async.wait_group 1;" ::: "memory")
#define CP_WAIT0()  asm volatile("cp.async.wait_group 0;" ::: "memory")

__device__ __forceinline__ void ldsm4(uint32_t* r, uint32_t addr) {
    asm volatile("ldmatrix.sync.aligned.m8n8.x4.shared.b16 {%0,%1,%2,%3}, [%4];"
                 : "=r"(r[0]), "=r"(r[1]), "=r"(r[2]), "=r"(r[3]) : "r"(addr));
}
__device__ __forceinline__ void mma16816(float* c, const uint32_t* a, const uint32_t* b) {
    asm volatile(
        "mma.sync.aligned.m16n8k16.row.col.f32.f16.f16.f32 "
        "{%0,%1,%2,%3},{%4,%5,%6,%7},{%8,%9},{%0,%1,%2,%3};"
        : "+f"(c[0]), "+f"(c[1]), "+f"(c[2]), "+f"(c[3])
        : "r"(a[0]), "r"(a[1]), "r"(a[2]), "r"(a[3]), "r"(b[0]), "r"(b[1]));
}

// ---------------- graph_id dtype detection ----------------
__global__ void detect_kernel(const int* p, int N) {
    int z = 1;
    for (int j = 0; j < 8; j++) {
        int idx = N - 1 - 2 * j;
        if (idx < 1) break;
        if ((idx & 1) == 0) idx--;
        if (idx >= 1 && p[idx] != 0) z = 0;
    }
    d_is64 = z;
}
__device__ __forceinline__ int get_gid(const void* p, int i) {
    if (d_is64) return (int)((const long long*)p)[i];
    return ((const int*)p)[i];
}
__global__ void starts_kernel(const void* gid, int N, int B) {
    int g = blockIdx.x * blockDim.x + threadIdx.x;
    if (g > B) return;
    int lo = 0, hi = N;
    while (lo < hi) {
        int mid = (lo + hi) >> 1;
        if (get_gid(gid, mid) < g) lo = mid + 1; else hi = mid;
    }
    d_starts[g] = lo;
}

// ---------------- convert nodes fp32 -> fp16 (one pass) ----------------
__global__ void convert_nodes(const float* __restrict__ nodes, int N) {
    int i = blockIdx.x * blockDim.x + threadIdx.x;   // one thread per 8 elements
    size_t total = (size_t)N * 32;
    if (i >= total) return;
    const float4* src = (const float4*)nodes + (size_t)i * 2;
    float4 a = src[0], b = src[1];
    __half2 h0 = __floats2half2_rn(a.x, a.y);
    __half2 h1 = __floats2half2_rn(a.z, a.w);
    __half2 h2 = __floats2half2_rn(b.x, b.y);
    __half2 h3 = __floats2half2_rn(b.z, b.w);
    uint4 out;
    out.x = *(uint32_t*)&h0; out.y = *(uint32_t*)&h1;
    out.z = *(uint32_t*)&h2; out.w = *(uint32_t*)&h3;
    ((uint4*)d_nodesh)[i] = out;
}

// ---------------- pack weights (fp16) + summed biases ----------------
__global__ void pack_kernel(const float* __restrict__ Wih0, const float* __restrict__ Whh0,
                            const float* __restrict__ bih0, const float* __restrict__ bhh0,
                            const float* __restrict__ Wih1, const float* __restrict__ Whh1,
                            const float* __restrict__ bih1, const float* __restrict__ bhh1) {
    int i = blockIdx.x * blockDim.x + threadIdx.x;
    if (i < 1024 * 768) {
        int j = i / 768, k = i % 768;
        float v = (k < 512) ? Wih0[j * 512 + k] : Whh0[j * 256 + (k - 512)];
        d_W0[i] = __float2half_rn(v);
    }
    if (i < 1024 * 512) {
        int j = i / 512, k = i % 512;
        float v = (k < 256) ? Wih1[j * 256 + k] : Whh1[j * 256 + (k - 256)];
        d_W1[i] = __float2half_rn(v);
    }
    if (i < 1024) {
        d_b0[i] = bih0[i] + bhh0[i];
        d_b1[i] = bih1[i] + bhh1[i];
    }
}

// ---------------- zero-init state ----------------
__global__ void init_kernel(int B) {
    int i = blockIdx.x * blockDim.x + threadIdx.x;
    __half z = __float2half_rn(0.f);
    if (i < B * 768) d_X0[i] = z;
    if (i < B * 512) d_X1[i] = z;
    if (i < B * 256) { d_c0[i] = 0.f; d_c1[i] = 0.f; d_q[i] = 0.f; }
}

// ---------------- attention: single-pass online softmax over fp16 nodes ----------------
// One CTA (256 threads, 8 warps) per graph. Lane handles elements [8*lane, 8*lane+8).
__global__ void attention_kernel(float* __restrict__ dout, int final_iter) {
    int g = blockIdx.x;
    int s = d_starts[g], en = d_starts[g + 1];
    __shared__ float qs[256];
    __shared__ float vsum[8][256];
    __shared__ float wm[8], ws[8], wscale[8];
    __shared__ float s_inv;
    int tid = threadIdx.x, lane = tid & 31, w = tid >> 5;

    qs[tid] = d_q[(size_t)g * 256 + tid];
    __syncthreads();

    // per-lane q slice: elements 8*lane .. 8*lane+7
    float qv[8];
    #pragma unroll
    for (int j = 0; j < 8; j++) qv[j] = qs[8 * lane + j];

    float m = -3.4e38f, ssum = 0.f;
    float v[8];
    #pragma unroll
    for (int j = 0; j < 8; j++) v[j] = 0.f;

    for (int n = s + w; n < en; n += 8) {
        uint4 pk = ((const uint4*)(d_nodesh + (size_t)n * 256))[lane];
        float2 f0 = __half22float2(*(__half2*)&pk.x);
        float2 f1 = __half22float2(*(__half2*)&pk.y);
        float2 f2 = __half22float2(*(__half2*)&pk.z);
        float2 f3 = __half22float2(*(__half2*)&pk.w);
        float x[8] = {f0.x, f0.y, f1.x, f1.y, f2.x, f2.y, f3.x, f3.y};

        float d = 0.f;
        #pragma unroll
        for (int j = 0; j < 8; j++) d = fmaf(x[j], qv[j], d);
        #pragma unroll
        for (int o = 16; o; o >>= 1) d += __shfl_xor_sync(0xffffffffu, d, o);

        float mn = fmaxf(m, d);
        float scale = __expf(m - mn);    // 0 on first row (m=-inf)
        float e = __expf(d - mn);
        ssum = ssum * scale + e;
        #pragma unroll
        for (int j = 0; j < 8; j++) v[j] = fmaf(v[j], scale, e * x[j]);
        m = mn;
    }

    if (lane == 0) { wm[w] = m; ws[w] = ssum; }
    {
        float4* dst = (float4*)&vsum[w][8 * lane];
        dst[0] = make_float4(v[0], v[1], v[2], v[3]);
        dst[1] = make_float4(v[4], v[5], v[6], v[7]);
    }
    __syncthreads();

    if (tid == 0) {
        float M = -3.4e38f;
        #pragma unroll
        for (int i = 0; i < 8; i++) if (ws[i] > 0.f) M = fmaxf(M, wm[i]);
        float S = 0.f;
        #pragma unroll
        for (int i = 0; i < 8; i++) {
            float sc = (ws[i] > 0.f) ? __expf(wm[i] - M) : 0.f;
            wscale[i] = sc;
            S += ws[i] * sc;
        }
        s_inv = (S > 0.f) ? 1.f / S : 0.f;
    }
    __syncthreads();

    float acc = 0.f;
    #pragma unroll
    for (int i = 0; i < 8; i++) acc = fmaf(vsum[i][tid], wscale[i], acc);
    acc *= s_inv;

    if (final_iter) {
        dout[(size_t)g * 512 + tid] = qs[tid];
        dout[(size_t)g * 512 + 256 + tid] = acc;
    } else {
        d_X0[(size_t)g * 768 + tid] = __float2half_rn(qs[tid]);
        d_X0[(size_t)g * 768 + 256 + tid] = __float2half_rn(acc);
    }
}

// ---------------- mma.sync fp16 GEMM: gates = X * W^T ----
// CTA tile 128x128, 8 warps (4m x 2n), warp tile 32x64, BK=32,
// 3-stage cp.async, one sync per K-iter.
#define ROWB 80                    // padded row bytes (conflict-free ldmatrix)
#define ARR  (128 * ROWB)          // 10240 B per array
#define STG  (2 * ARR)             // 20480 B per stage (A, B)
#define SMEM_GEMM (3 * STG)        // 61440 B

__global__ __launch_bounds__(256, 1) void mma_gates(int layer, int B) {
    const __half* __restrict__ Ag = layer ? d_X1 : d_X0;
    const __half* __restrict__ Wg = layer ? d_W1 : d_W0;
    const int K = layer ? 512 : 768;

    extern __shared__ __half sm[];
    const uint32_t sbase = smem_u32(sm);

    const int tid = threadIdx.x, lane = tid & 31, warp = tid >> 5;
    const int wm = warp >> 1, wn = warp & 1;
    const int tm = blockIdx.y, tn = blockIdx.x;

    float c[2][8][4];
    #pragma unroll
    for (int i = 0; i < 2; i++)
        #pragma unroll
        for (int j = 0; j < 8; j++)
            #pragma unroll
            for (int k = 0; k < 4; k++) c[i][j][k] = 0.f;

    int idx0 = tid, idx1 = tid + 256;
    int row0 = idx0 >> 2, ch0 = idx0 & 3;
    int row1 = idx1 >> 2, ch1 = idx1 & 3;
    int ar0 = tm * 128 + row0; if (ar0 >= B) ar0 = B - 1;
    int ar1 = tm * 128 + row1; if (ar1 >= B) ar1 = B - 1;
    int br0 = tn * 128 + row0;
    int br1 = tn * 128 + row1;

    const int niter = K >> 5;

    #define ISSUE(I, BUF) do {                                                   \
        int _k0 = (I) << 5;                                                      \
        uint32_t _d0 = sbase + (BUF) * STG + row0 * ROWB + ch0 * 16;             \
        uint32_t _d1 = sbase + (BUF) * STG + row1 * ROWB + ch1 * 16;             \
        size_t _a0 = (size_t)ar0 * K + _k0 + ch0 * 8;                            \
        size_t _a1 = (size_t)ar1 * K + _k0 + ch1 * 8;                            \
        size_t _b0 = (size_t)br0 * K + _k0 + ch0 * 8;                            \
        size_t _b1 = (size_t)br1 * K + _k0 + ch1 * 8;                            \
        cp16(_d0 + 0 * ARR, Ag + _a0);  cp16(_d1 + 0 * ARR, Ag + _a1);           \
        cp16(_d0 + 1 * ARR, Wg + _b0);  cp16(_d1 + 1 * ARR, Wg + _b1);           \
        CP_COMMIT();                                                             \
    } while (0)

    ISSUE(0, 0);
    ISSUE(1, 1);

    const int m0 = wm * 32, n0 = wn * 64;
    const uint32_t a_row = m0 + (lane & 15);
    const uint32_t a_koff = (lane >> 4) * 16;
    const uint32_t b_row = n0 + (lane & 7) + ((lane >> 4) << 3);
    const uint32_t b_koff = ((lane >> 3) & 1) * 16;

    int buf = 0, nbuf = 2;
    for (int i = 0; i < niter; i++) {
        if (i + 1 < niter) CP_WAIT1(); else CP_WAIT0();
        __syncthreads();
        if (i + 2 < niter) ISSUE(i + 2, nbuf);

        uint32_t sb = sbase + buf * STG;
        uint32_t aA = sb + 0 * ARR;
        uint32_t aB = sb + 1 * ARR;

        #pragma unroll
        for (int kk = 0; kk < 2; kk++) {
            uint32_t kb = kk * 32;
            uint32_t ah[2][4], bh[4][4];
            ldsm4(ah[0], aA + a_row * ROWB + kb + a_koff);
            ldsm4(ah[1], aA + (a_row + 16) * ROWB + kb + a_koff);
            #pragma unroll
            for (int nb = 0; nb < 4; nb++)
                ldsm4(bh[nb], aB + (b_row + nb * 16) * ROWB + kb + b_koff);
            #pragma unroll
            for (int mi = 0; mi < 2; mi++)
                #pragma unroll
                for (int nb = 0; nb < 4; nb++)
                    #pragma unroll
                    for (int h = 0; h < 2; h++) {
                        int n8 = nb * 2 + h;
                        mma16816(c[mi][n8], ah[mi], &bh[nb][h * 2]);
                    }
        }
        buf = (buf == 2) ? 0 : buf + 1;
        nbuf = (nbuf == 2) ? 0 : nbuf + 1;
    }

    // epilogue: write fp32 gates
    int g = lane >> 2, qt = lane & 3;
    #pragma unroll
    for (int mi = 0; mi < 2; mi++) {
        #pragma unroll
        for (int n8 = 0; n8 < 8; n8++) {
            int row = tm * 128 + m0 + mi * 16 + g;
            int col = tn * 128 + n0 + n8 * 8 + qt * 2;
            if (row < B)
                *(float2*)&d_gates[(size_t)row * 1024 + col] = make_float2(c[mi][n8][0], c[mi][n8][1]);
            if (row + 8 < B)
                *(float2*)&d_gates[(size_t)(row + 8) * 1024 + col] = make_float2(c[mi][n8][2], c[mi][n8][3]);
        }
    }
    #undef ISSUE
}

// ---------------- LSTM pointwise: gates -> (h, c), writes fp16 inputs ----
__global__ void lstm_act_kernel(int layer, int B) {
    int idx = blockIdx.x * blockDim.x + threadIdx.x;
    if (idx >= B * 256) return;
    int b = idx >> 8, t = idx & 255;
    const float* gr = d_gates + (size_t)b * 1024;
    const float* bs = (layer == 0) ? d_b0 : d_b1;
    float* c = (layer == 0) ? d_c0 : d_c1;

    float gi = gr[t]       + bs[t];
    float gf = gr[t + 256] + bs[t + 256];
    float gg = gr[t + 512] + bs[t + 512];
    float go = gr[t + 768] + bs[t + 768];

    float si = 1.f / (1.f + expf(-gi));
    float sf = 1.f / (1.f + expf(-gf));
    float tg = tanhf(gg);
    float so = 1.f / (1.f + expf(-go));

    float cn = sf * c[idx] + si * tg;
    c[idx] = cn;
    float hn = so * tanhf(cn);

    __half h = __float2half_rn(hn);
    if (layer == 0) {
        d_X0[(size_t)b * 768 + 512 + t] = h;
        d_X1[(size_t)b * 512 + t]       = h;
    } else {
        d_X1[(size_t)b * 512 + 256 + t] = h;
        d_q[idx] = hn;
    }
}

// ---------------- host launcher ----------------
extern "C" void kernel_launch(void* const* d_in, const int* in_sizes, int n_in,
                              void* d_out, int out_size) {
    const float* nodes = (const float*)d_in[0];
    const void*  gid   = d_in[1];
    int N = in_sizes[1];

    int wbase = (in_sizes[2] == 1) ? 3 : 2;
    const float* Wih0 = (const float*)d_in[wbase + 0];
    const float* Whh0 = (const float*)d_in[wbase + 1];
    const float* bih0 = (const float*)d_in[wbase + 2];
    const float* bhh0 = (const float*)d_in[wbase + 3];
    const float* Wih1 = (const float*)d_in[wbase + 4];
    const float* Whh1 = (const float*)d_in[wbase + 5];
    const float* bih1 = (const float*)d_in[wbase + 6];
    const float* bhh1 = (const float*)d_in[wbase + 7];

    int B = out_size / (2 * Hh);
    float* out = (float*)d_out;

    cudaFuncSetAttribute(mma_gates, cudaFuncAttributeMaxDynamicSharedMemorySize, SMEM_GEMM);

    detect_kernel<<<1, 1>>>((const int*)gid, N);
    starts_kernel<<<(B + 1 + 255) / 256, 256>>>(gid, N, B);
    convert_nodes<<<(N * 32 + 255) / 256, 256>>>(nodes, N);
    pack_kernel<<<(1024 * 768 + 255) / 256, 256>>>(Wih0, Whh0, bih0, bhh0,
                                                   Wih1, Whh1, bih1, bhh1);
    init_kernel<<<(B * 768 + 255) / 256, 256>>>(B);

    dim3 gemm_grid(1024 / 128, (B + 127) / 128);
    const int M_ITERS = 6;
    for (int i = 0; i < M_ITERS; i++) {
        int final_iter = (i == M_ITERS - 1) ? 1 : 0;
        attention_kernel<<<B, 256>>>(out, final_iter);
        if (!final_iter) {
            mma_gates<<<gemm_grid, 256, SMEM_GEMM>>>(0, B);
            lstm_act_kernel<<<(B * 256 + 255) / 256, 256>>>(0, B);
            mma_gates<<<gemm_grid, 256, SMEM_GEMM>>>(1, B);
            lstm_act_kernel<<<(B * 256 + 255) / 256, 256>>>(1, B);
        }
    }
}

// round 13
// speedup vs baseline: 2.1597x; 1.1186x over previous
#include <cuda_runtime.h>
#include <cuda_fp16.h>
#include <math.h>
#include <stdint.h>

#define Hh 256
#define NMAX 262144
#define BMAX 4096

// ---------------- device scratch (no allocations allowed) ----------------
__device__ int    d_starts[BMAX + 1];
__device__ int    d_is64;
__device__ float  d_gates[BMAX * 1024];
__device__ float  d_c0[BMAX * 256];
__device__ float  d_c1[BMAX * 256];
__device__ __half d_nodesh[(size_t)NMAX * 256];   // fp16 copy of nodes
// fp16 operands
__device__ __half d_X0[BMAX * 768];          // [q_star(512)|h0(256)]
__device__ __half d_X1[BMAX * 512];          // [h0(256)|h1(256)]
__device__ __half d_W0[1024 * 768];          // [Wih0|Whh0]
__device__ __half d_W1[1024 * 512];          // [Wih1|Whh1]
__device__ float  d_b0[1024], d_b1[1024];

// ---------------- small helpers ----------------
__device__ __forceinline__ uint32_t smem_u32(const void* p) {
    uint32_t a;
    asm("{ .reg .u64 t; cvta.to.shared.u64 t, %1; cvt.u32.u64 %0, t; }" : "=r"(a) : "l"(p));
    return a;
}
__device__ __forceinline__ void cp16(uint32_t dst, const void* src) {
    asm volatile("cp.async.cg.shared.global [%0], [%1], 16;" :: "r"(dst), "l"(src));
}
#define CP_COMMIT() asm volatile("cp.async.commit_group;" ::: "memory")
#define CP_WAIT1()  asm volatile("cp.async.wait_group 1;" ::: "memory")
#define CP_WAIT0()  asm volatile("cp.async.wait_group 0;" ::: "memory")

__device__ __forceinline__ void ldsm4(uint32_t* r, uint32_t addr) {
    asm volatile("ldmatrix.sync.aligned.m8n8.x4.shared.b16 {%0,%1,%2,%3}, [%4];"
                 : "=r"(r[0]), "=r"(r[1]), "=r"(r[2]), "=r"(r[3]) : "r"(addr));
}
__device__ __forceinline__ void mma16816(float* c, const uint32_t* a, const uint32_t* b) {
    asm volatile(
        "mma.sync.aligned.m16n8k16.row.col.f32.f16.f16.f32 "
        "{%0,%1,%2,%3},{%4,%5,%6,%7},{%8,%9},{%0,%1,%2,%3};"
        : "+f"(c[0]), "+f"(c[1]), "+f"(c[2]), "+f"(c[3])
        : "r"(a[0]), "r"(a[1]), "r"(a[2]), "r"(a[3]), "r"(b[0]), "r"(b[1]));
}

// ---------------- graph_id dtype detection ----------------
__global__ void detect_kernel(const int* p, int N) {
    int z = 1;
    for (int j = 0; j < 8; j++) {
        int idx = N - 1 - 2 * j;
        if (idx < 1) break;
        if ((idx & 1) == 0) idx--;
        if (idx >= 1 && p[idx] != 0) z = 0;
    }
    d_is64 = z;
}
__device__ __forceinline__ int get_gid(const void* p, int i) {
    if (d_is64) return (int)((const long long*)p)[i];
    return ((const int*)p)[i];
}
__global__ void starts_kernel(const void* gid, int N, int B) {
    int g = blockIdx.x * blockDim.x + threadIdx.x;
    if (g > B) return;
    int lo = 0, hi = N;
    while (lo < hi) {
        int mid = (lo + hi) >> 1;
        if (get_gid(gid, mid) < g) lo = mid + 1; else hi = mid;
    }
    d_starts[g] = lo;
}

// ---------------- pack weights (fp16) + summed biases ----------------
__global__ void pack_kernel(const float* __restrict__ Wih0, const float* __restrict__ Whh0,
                            const float* __restrict__ bih0, const float* __restrict__ bhh0,
                            const float* __restrict__ Wih1, const float* __restrict__ Whh1,
                            const float* __restrict__ bih1, const float* __restrict__ bhh1) {
    int i = blockIdx.x * blockDim.x + threadIdx.x;
    if (i < 1024 * 768) {
        int j = i / 768, k = i % 768;
        float v = (k < 512) ? Wih0[j * 512 + k] : Whh0[j * 256 + (k - 512)];
        d_W0[i] = __float2half_rn(v);
    }
    if (i < 1024 * 512) {
        int j = i / 512, k = i % 512;
        float v = (k < 256) ? Wih1[j * 256 + k] : Whh1[j * 256 + (k - 256)];
        d_W1[i] = __float2half_rn(v);
    }
    if (i < 1024) {
        d_b0[i] = bih0[i] + bhh0[i];
        d_b1[i] = bih1[i] + bhh1[i];
    }
}

// ---------------- zero-init state ----------------
__global__ void init_kernel(int B) {
    int i = blockIdx.x * blockDim.x + threadIdx.x;
    __half z = __float2half_rn(0.f);
    if (i < B * 768) d_X0[i] = z;
    if (i < B * 512) d_X1[i] = z;
    if (i < B * 256) { d_c0[i] = 0.f; d_c1[i] = 0.f; }
}

// ---------------- iteration 0: convert nodes->fp16 AND compute mean readout ----
// q = 0 => softmax uniform => r = mean(rows). One CTA per graph.
__global__ void convert_mean_kernel(const float* __restrict__ nodes) {
    int g = blockIdx.x;
    int s = d_starts[g], en = d_starts[g + 1];
    int len = en - s;
    __shared__ float vsum[8][256];
    int tid = threadIdx.x, lane = tid & 31, w = tid >> 5;

    float v[8];
    #pragma unroll
    for (int j = 0; j < 8; j++) v[j] = 0.f;

    for (int n = s + w; n < en; n += 8) {
        const float4* rp = (const float4*)(nodes + (size_t)n * 256);
        float4 a = rp[2 * lane], b = rp[2 * lane + 1];
        __half2 h0 = __floats2half2_rn(a.x, a.y);
        __half2 h1 = __floats2half2_rn(a.z, a.w);
        __half2 h2 = __floats2half2_rn(b.x, b.y);
        __half2 h3 = __floats2half2_rn(b.z, b.w);
        uint4 pk;
        pk.x = *(uint32_t*)&h0; pk.y = *(uint32_t*)&h1;
        pk.z = *(uint32_t*)&h2; pk.w = *(uint32_t*)&h3;
        ((uint4*)(d_nodesh + (size_t)n * 256))[lane] = pk;
        v[0] += a.x; v[1] += a.y; v[2] += a.z; v[3] += a.w;
        v[4] += b.x; v[5] += b.y; v[6] += b.z; v[7] += b.w;
    }
    {
        float4* dst = (float4*)&vsum[w][8 * lane];
        dst[0] = make_float4(v[0], v[1], v[2], v[3]);
        dst[1] = make_float4(v[4], v[5], v[6], v[7]);
    }
    __syncthreads();

    float inv = (len > 0) ? 1.f / (float)len : 0.f;
    float acc = 0.f;
    #pragma unroll
    for (int i = 0; i < 8; i++) acc += vsum[i][tid];
    acc *= inv;

    // q_star = [0 | mean]
    d_X0[(size_t)g * 768 + tid] = __float2half_rn(0.f);
    d_X0[(size_t)g * 768 + 256 + tid] = __float2half_rn(acc);
}

// ---------------- attention (iters 1..5): fused act1 prologue + online softmax ----
// Prologue: CTA g computes h1/c1 from d_gates (previous gemm1) -> q.
// Main: single-pass online softmax over fp16 nodes, rows unrolled x2.
__global__ void attention_kernel(float* __restrict__ dout, int final_iter) {
    int g = blockIdx.x;
    int s = d_starts[g], en = d_starts[g + 1];
    __shared__ float qs[256];
    __shared__ float vsum[8][256];
    __shared__ float wmx[8], wsx[8], wscale[8];
    __shared__ float s_inv;
    int tid = threadIdx.x, lane = tid & 31, w = tid >> 5;

    // ---- fused LSTM layer-1 activation: gates -> (h1, c1); q = h1 ----
    {
        const float* gr = d_gates + (size_t)g * 1024;
        float gi = gr[tid]       + d_b1[tid];
        float gf = gr[tid + 256] + d_b1[tid + 256];
        float gg = gr[tid + 512] + d_b1[tid + 512];
        float go = gr[tid + 768] + d_b1[tid + 768];
        float si = 1.f / (1.f + expf(-gi));
        float sf = 1.f / (1.f + expf(-gf));
        float tg = tanhf(gg);
        float so = 1.f / (1.f + expf(-go));
        size_t ci = (size_t)g * 256 + tid;
        float cn = sf * d_c1[ci] + si * tg;
        d_c1[ci] = cn;
        float hn = so * tanhf(cn);
        qs[tid] = hn;
        d_X1[(size_t)g * 512 + 256 + tid] = __float2half_rn(hn);  // h1 for next gemm1
    }
    __syncthreads();

    float qv[8];
    #pragma unroll
    for (int j = 0; j < 8; j++) qv[j] = qs[8 * lane + j];

    float m = -3.4e38f, ssum = 0.f;
    float v[8];
    #pragma unroll
    for (int j = 0; j < 8; j++) v[j] = 0.f;

    int n = s + w;
    // pairs: rows n and n+8 (warp stride 16)
    for (; n + 8 < en; n += 16) {
        uint4 p1 = ((const uint4*)(d_nodesh + (size_t)n * 256))[lane];
        uint4 p2 = ((const uint4*)(d_nodesh + (size_t)(n + 8) * 256))[lane];
        float2 a0 = __half22float2(*(__half2*)&p1.x);
        float2 a1 = __half22float2(*(__half2*)&p1.y);
        float2 a2 = __half22float2(*(__half2*)&p1.z);
        float2 a3 = __half22float2(*(__half2*)&p1.w);
        float2 b0 = __half22float2(*(__half2*)&p2.x);
        float2 b1 = __half22float2(*(__half2*)&p2.y);
        float2 b2 = __half22float2(*(__half2*)&p2.z);
        float2 b3 = __half22float2(*(__half2*)&p2.w);
        float x1[8] = {a0.x, a0.y, a1.x, a1.y, a2.x, a2.y, a3.x, a3.y};
        float x2[8] = {b0.x, b0.y, b1.x, b1.y, b2.x, b2.y, b3.x, b3.y};

        float d1 = 0.f, d2 = 0.f;
        #pragma unroll
        for (int j = 0; j < 8; j++) {
            d1 = fmaf(x1[j], qv[j], d1);
            d2 = fmaf(x2[j], qv[j], d2);
        }
        #pragma unroll
        for (int o = 16; o; o >>= 1) {
            d1 += __shfl_xor_sync(0xffffffffu, d1, o);
            d2 += __shfl_xor_sync(0xffffffffu, d2, o);
        }

        float mn = fmaxf(m, fmaxf(d1, d2));
        float scale = __expf(m - mn);
        float e1 = __expf(d1 - mn);
        float e2 = __expf(d2 - mn);
        ssum = ssum * scale + e1 + e2;
        #pragma unroll
        for (int j = 0; j < 8; j++)
            v[j] = fmaf(fmaf(v[j], scale, e1 * x1[j]), 1.f, e2 * x2[j]);
        m = mn;
    }
    // tail single row
    for (; n < en; n += 8) {
        uint4 p1 = ((const uint4*)(d_nodesh + (size_t)n * 256))[lane];
        float2 a0 = __half22float2(*(__half2*)&p1.x);
        float2 a1 = __half22float2(*(__half2*)&p1.y);
        float2 a2 = __half22float2(*(__half2*)&p1.z);
        float2 a3 = __half22float2(*(__half2*)&p1.w);
        float x1[8] = {a0.x, a0.y, a1.x, a1.y, a2.x, a2.y, a3.x, a3.y};
        float d1 = 0.f;
        #pragma unroll
        for (int j = 0; j < 8; j++) d1 = fmaf(x1[j], qv[j], d1);
        #pragma unroll
        for (int o = 16; o; o >>= 1) d1 += __shfl_xor_sync(0xffffffffu, d1, o);
        float mn = fmaxf(m, d1);
        float scale = __expf(m - mn);
        float e1 = __expf(d1 - mn);
        ssum = ssum * scale + e1;
        #pragma unroll
        for (int j = 0; j < 8; j++) v[j] = fmaf(v[j], scale, e1 * x1[j]);
        m = mn;
    }

    if (lane == 0) { wmx[w] = m; wsx[w] = ssum; }
    {
        float4* dst = (float4*)&vsum[w][8 * lane];
        dst[0] = make_float4(v[0], v[1], v[2], v[3]);
        dst[1] = make_float4(v[4], v[5], v[6], v[7]);
    }
    __syncthreads();

    if (tid == 0) {
        float M = -3.4e38f;
        #pragma unroll
        for (int i = 0; i < 8; i++) if (wsx[i] > 0.f) M = fmaxf(M, wmx[i]);
        float S = 0.f;
        #pragma unroll
        for (int i = 0; i < 8; i++) {
            float sc = (wsx[i] > 0.f) ? __expf(wmx[i] - M) : 0.f;
            wscale[i] = sc;
            S += wsx[i] * sc;
        }
        s_inv = (S > 0.f) ? 1.f / S : 0.f;
    }
    __syncthreads();

    float acc = 0.f;
    #pragma unroll
    for (int i = 0; i < 8; i++) acc = fmaf(vsum[i][tid], wscale[i], acc);
    acc *= s_inv;

    if (final_iter) {
        dout[(size_t)g * 512 + tid] = qs[tid];
        dout[(size_t)g * 512 + 256 + tid] = acc;
    } else {
        d_X0[(size_t)g * 768 + tid] = __float2half_rn(qs[tid]);
        d_X0[(size_t)g * 768 + 256 + tid] = __float2half_rn(acc);
    }
}

// ---------------- mma.sync fp16 GEMM: gates = X * W^T ----
#define ROWB 80                    // padded row bytes (conflict-free ldmatrix)
#define ARR  (128 * ROWB)          // 10240 B per array
#define STG  (2 * ARR)             // 20480 B per stage (A, B)
#define SMEM_GEMM (3 * STG)        // 61440 B

__global__ __launch_bounds__(256, 1) void mma_gates(int layer, int B) {
    const __half* __restrict__ Ag = layer ? d_X1 : d_X0;
    const __half* __restrict__ Wg = layer ? d_W1 : d_W0;
    const int K = layer ? 512 : 768;

    extern __shared__ __half sm[];
    const uint32_t sbase = smem_u32(sm);

    const int tid = threadIdx.x, lane = tid & 31, warp = tid >> 5;
    const int wm = warp >> 1, wn = warp & 1;
    const int tm = blockIdx.y, tn = blockIdx.x;

    float c[2][8][4];
    #pragma unroll
    for (int i = 0; i < 2; i++)
        #pragma unroll
        for (int j = 0; j < 8; j++)
            #pragma unroll
            for (int k = 0; k < 4; k++) c[i][j][k] = 0.f;

    int idx0 = tid, idx1 = tid + 256;
    int row0 = idx0 >> 2, ch0 = idx0 & 3;
    int row1 = idx1 >> 2, ch1 = idx1 & 3;
    int ar0 = tm * 128 + row0; if (ar0 >= B) ar0 = B - 1;
    int ar1 = tm * 128 + row1; if (ar1 >= B) ar1 = B - 1;
    int br0 = tn * 128 + row0;
    int br1 = tn * 128 + row1;

    const int niter = K >> 5;

    #define ISSUE(I, BUF) do {                                                   \
        int _k0 = (I) << 5;                                                      \
        uint32_t _d0 = sbase + (BUF) * STG + row0 * ROWB + ch0 * 16;             \
        uint32_t _d1 = sbase + (BUF) * STG + row1 * ROWB + ch1 * 16;             \
        size_t _a0 = (size_t)ar0 * K + _k0 + ch0 * 8;                            \
        size_t _a1 = (size_t)ar1 * K + _k0 + ch1 * 8;                            \
        size_t _b0 = (size_t)br0 * K + _k0 + ch0 * 8;                            \
        size_t _b1 = (size_t)br1 * K + _k0 + ch1 * 8;                            \
        cp16(_d0 + 0 * ARR, Ag + _a0);  cp16(_d1 + 0 * ARR, Ag + _a1);           \
        cp16(_d0 + 1 * ARR, Wg + _b0);  cp16(_d1 + 1 * ARR, Wg + _b1);           \
        CP_COMMIT();                                                             \
    } while (0)

    ISSUE(0, 0);
    ISSUE(1, 1);

    const int m0 = wm * 32, n0 = wn * 64;
    const uint32_t a_row = m0 + (lane & 15);
    const uint32_t a_koff = (lane >> 4) * 16;
    const uint32_t b_row = n0 + (lane & 7) + ((lane >> 4) << 3);
    const uint32_t b_koff = ((lane >> 3) & 1) * 16;

    int buf = 0, nbuf = 2;
    for (int i = 0; i < niter; i++) {
        if (i + 1 < niter) CP_WAIT1(); else CP_WAIT0();
        __syncthreads();
        if (i + 2 < niter) ISSUE(i + 2, nbuf);

        uint32_t sb = sbase + buf * STG;
        uint32_t aA = sb + 0 * ARR;
        uint32_t aB = sb + 1 * ARR;

        #pragma unroll
        for (int kk = 0; kk < 2; kk++) {
            uint32_t kb = kk * 32;
            uint32_t ah[2][4], bh[4][4];
            ldsm4(ah[0], aA + a_row * ROWB + kb + a_koff);
            ldsm4(ah[1], aA + (a_row + 16) * ROWB + kb + a_koff);
            #pragma unroll
            for (int nb = 0; nb < 4; nb++)
                ldsm4(bh[nb], aB + (b_row + nb * 16) * ROWB + kb + b_koff);
            #pragma unroll
            for (int mi = 0; mi < 2; mi++)
                #pragma unroll
                for (int nb = 0; nb < 4; nb++)
                    #pragma unroll
                    for (int h = 0; h < 2; h++) {
                        int n8 = nb * 2 + h;
                        mma16816(c[mi][n8], ah[mi], &bh[nb][h * 2]);
                    }
        }
        buf = (buf == 2) ? 0 : buf + 1;
        nbuf = (nbuf == 2) ? 0 : nbuf + 1;
    }

    // epilogue: write fp32 gates
    int g = lane >> 2, qt = lane & 3;
    #pragma unroll
    for (int mi = 0; mi < 2; mi++) {
        #pragma unroll
        for (int n8 = 0; n8 < 8; n8++) {
            int row = tm * 128 + m0 + mi * 16 + g;
            int col = tn * 128 + n0 + n8 * 8 + qt * 2;
            if (row < B)
                *(float2*)&d_gates[(size_t)row * 1024 + col] = make_float2(c[mi][n8][0], c[mi][n8][1]);
            if (row + 8 < B)
                *(float2*)&d_gates[(size_t)(row + 8) * 1024 + col] = make_float2(c[mi][n8][2], c[mi][n8][3]);
        }
    }
    #undef ISSUE
}

// ---------------- LSTM layer-0 pointwise: gates -> (h0, c0), writes fp16 inputs ----
__global__ void lstm_act0_kernel(int B) {
    int idx = blockIdx.x * blockDim.x + threadIdx.x;
    if (idx >= B * 256) return;
    int b = idx >> 8, t = idx & 255;
    const float* gr = d_gates + (size_t)b * 1024;

    float gi = gr[t]       + d_b0[t];
    float gf = gr[t + 256] + d_b0[t + 256];
    float gg = gr[t + 512] + d_b0[t + 512];
    float go = gr[t + 768] + d_b0[t + 768];

    float si = 1.f / (1.f + expf(-gi));
    float sf = 1.f / (1.f + expf(-gf));
    float tg = tanhf(gg);
    float so = 1.f / (1.f + expf(-go));

    float cn = sf * d_c0[idx] + si * tg;
    d_c0[idx] = cn;
    float hn = so * tanhf(cn);

    __half h = __float2half_rn(hn);
    d_X0[(size_t)b * 768 + 512 + t] = h;
    d_X1[(size_t)b * 512 + t]       = h;
}

// ---------------- host launcher ----------------
extern "C" void kernel_launch(void* const* d_in, const int* in_sizes, int n_in,
                              void* d_out, int out_size) {
    const float* nodes = (const float*)d_in[0];
    const void*  gid   = d_in[1];
    int N = in_sizes[1];

    int wbase = (in_sizes[2] == 1) ? 3 : 2;
    const float* Wih0 = (const float*)d_in[wbase + 0];
    const float* Whh0 = (const float*)d_in[wbase + 1];
    const float* bih0 = (const float*)d_in[wbase + 2];
    const float* bhh0 = (const float*)d_in[wbase + 3];
    const float* Wih1 = (const float*)d_in[wbase + 4];
    const float* Whh1 = (const float*)d_in[wbase + 5];
    const float* bih1 = (const float*)d_in[wbase + 6];
    const float* bhh1 = (const float*)d_in[wbase + 7];

    int B = out_size / (2 * Hh);
    float* out = (float*)d_out;

    cudaFuncSetAttribute(mma_gates, cudaFuncAttributeMaxDynamicSharedMemorySize, SMEM_GEMM);

    detect_kernel<<<1, 1>>>((const int*)gid, N);
    starts_kernel<<<(B + 1 + 255) / 256, 256>>>(gid, N, B);
    pack_kernel<<<(1024 * 768 + 255) / 256, 256>>>(Wih0, Whh0, bih0, bhh0,
                                                   Wih1, Whh1, bih1, bhh1);
    init_kernel<<<(B * 768 + 255) / 256, 256>>>(B);

    dim3 gemm_grid(1024 / 128, (B + 127) / 128);
    const int M_ITERS = 6;
    for (int i = 0; i < M_ITERS; i++) {
        int final_iter = (i == M_ITERS - 1) ? 1 : 0;
        if (i == 0) {
            convert_mean_kernel<<<B, 256>>>(nodes);   // q=0: r = mean, emit fp16 copy
        } else {
            attention_kernel<<<B, 256>>>(out, final_iter);  // fused act1 prologue
        }
        if (!final_iter) {
            mma_gates<<<gemm_grid, 256, SMEM_GEMM>>>(0, B);
            lstm_act0_kernel<<<(B * 256 + 255) / 256, 256>>>(B);
            mma_gates<<<gemm_grid, 256, SMEM_GEMM>>>(1, B);
        }
    }
}

// round 14
// speedup vs baseline: 2.4251x; 1.1229x over previous
#include <cuda_runtime.h>
#include <cuda_fp16.h>
#include <math.h>
#include <stdint.h>

#define Hh 256
#define NMAX 262144
#define BMAX 4096

// ---------------- device scratch (no allocations allowed) ----------------
__device__ int    d_starts[BMAX + 1];
__device__ float  d_gates[BMAX * 1024];
__device__ float  d_c0[BMAX * 256];
__device__ float  d_c1[BMAX * 256];
__device__ __half d_nodesh[(size_t)NMAX * 256];   // fp16 copy of nodes
// fp16 operands
__device__ __half d_X0[BMAX * 768];          // [q_star(512)|h0(256)]
__device__ __half d_X1[BMAX * 512];          // [h0(256)|h1(256)]
__device__ __half d_W0[1024 * 768];          // [Wih0|Whh0]
__device__ __half d_W1[1024 * 512];          // [Wih1|Whh1]
__device__ float  d_b0[1024], d_b1[1024];

// ---------------- small helpers ----------------
__device__ __forceinline__ uint32_t smem_u32(const void* p) {
    uint32_t a;
    asm("{ .reg .u64 t; cvta.to.shared.u64 t, %1; cvt.u32.u64 %0, t; }" : "=r"(a) : "l"(p));
    return a;
}
__device__ __forceinline__ void cp16(uint32_t dst, const void* src) {
    asm volatile("cp.async.cg.shared.global [%0], [%1], 16;" :: "r"(dst), "l"(src));
}
#define CP_COMMIT() asm volatile("cp.async.commit_group;" ::: "memory")
#define CP_WAIT1()  asm volatile("cp.async.wait_group 1;" ::: "memory")
#define CP_WAIT0()  asm volatile("cp.async.wait_group 0;" ::: "memory")

__device__ __forceinline__ void ldsm4(uint32_t* r, uint32_t addr) {
    asm volatile("ldmatrix.sync.aligned.m8n8.x4.shared.b16 {%0,%1,%2,%3}, [%4];"
                 : "=r"(r[0]), "=r"(r[1]), "=r"(r[2]), "=r"(r[3]) : "r"(addr));
}
__device__ __forceinline__ void mma16816(float* c, const uint32_t* a, const uint32_t* b) {
    asm volatile(
        "mma.sync.aligned.m16n8k16.row.col.f32.f16.f16.f32 "
        "{%0,%1,%2,%3},{%4,%5,%6,%7},{%8,%9},{%0,%1,%2,%3};"
        : "+f"(c[0]), "+f"(c[1]), "+f"(c[2]), "+f"(c[3])
        : "r"(a[0]), "r"(a[1]), "r"(a[2]), "r"(a[3]), "r"(b[0]), "r"(b[1]));
}

// ---------------- starts (with inline graph_id dtype sniff) ----------------
__global__ void starts_kernel(const int* p, int N, int B) {
    int g = blockIdx.x * blockDim.x + threadIdx.x;
    if (g > B) return;
    // int64 detection: odd int32 words near the tail are 0 iff data is int64 (<2^31)
    int is64 = 1;
    for (int j = 0; j < 8; j++) {
        int idx = N - 1 - 2 * j;
        if (idx < 1) break;
        if ((idx & 1) == 0) idx--;
        if (idx >= 1 && p[idx] != 0) is64 = 0;
    }
    const long long* p64 = (const long long*)p;
    int lo = 0, hi = N;
    while (lo < hi) {
        int mid = (lo + hi) >> 1;
        int v = is64 ? (int)p64[mid] : p[mid];
        if (v < g) lo = mid + 1; else hi = mid;
    }
    d_starts[g] = lo;
}

// ---------------- pack weights (fp16) + summed biases + c-state init ----------------
__global__ void pack_kernel(const float* __restrict__ Wih0, const float* __restrict__ Whh0,
                            const float* __restrict__ bih0, const float* __restrict__ bhh0,
                            const float* __restrict__ Wih1, const float* __restrict__ Whh1,
                            const float* __restrict__ bih1, const float* __restrict__ bhh1,
                            int B) {
    int i = blockIdx.x * blockDim.x + threadIdx.x;
    if (i < 1024 * 768) {
        int j = i / 768, k = i % 768;
        float v = (k < 512) ? Wih0[j * 512 + k] : Whh0[j * 256 + (k - 512)];
        d_W0[i] = __float2half_rn(v);
    }
    if (i < 1024 * 512) {
        int j = i / 512, k = i % 512;
        float v = (k < 256) ? Wih1[j * 256 + k] : Whh1[j * 256 + (k - 256)];
        d_W1[i] = __float2half_rn(v);
    }
    if (i < 1024) {
        d_b0[i] = bih0[i] + bhh0[i];
        d_b1[i] = bih1[i] + bhh1[i];
    }
    if (i < B * 256) { d_c0[i] = 0.f; d_c1[i] = 0.f; }
}

// ---------------- iteration 0: convert nodes->fp16 AND compute mean readout ----
// q = 0 => softmax uniform => r = mean(rows). One CTA per graph.
__global__ void convert_mean_kernel(const float* __restrict__ nodes) {
    int g = blockIdx.x;
    int s = d_starts[g], en = d_starts[g + 1];
    int len = en - s;
    __shared__ float vsum[8][256];
    int tid = threadIdx.x, lane = tid & 31, w = tid >> 5;

    float v[8];
    #pragma unroll
    for (int j = 0; j < 8; j++) v[j] = 0.f;

    for (int n = s + w; n < en; n += 8) {
        const float4* rp = (const float4*)(nodes + (size_t)n * 256);
        float4 a = rp[2 * lane], b = rp[2 * lane + 1];
        __half2 h0 = __floats2half2_rn(a.x, a.y);
        __half2 h1 = __floats2half2_rn(a.z, a.w);
        __half2 h2 = __floats2half2_rn(b.x, b.y);
        __half2 h3 = __floats2half2_rn(b.z, b.w);
        uint4 pk;
        pk.x = *(uint32_t*)&h0; pk.y = *(uint32_t*)&h1;
        pk.z = *(uint32_t*)&h2; pk.w = *(uint32_t*)&h3;
        ((uint4*)(d_nodesh + (size_t)n * 256))[lane] = pk;
        v[0] += a.x; v[1] += a.y; v[2] += a.z; v[3] += a.w;
        v[4] += b.x; v[5] += b.y; v[6] += b.z; v[7] += b.w;
    }
    {
        float4* dst = (float4*)&vsum[w][8 * lane];
        dst[0] = make_float4(v[0], v[1], v[2], v[3]);
        dst[1] = make_float4(v[4], v[5], v[6], v[7]);
    }
    __syncthreads();

    float inv = (len > 0) ? 1.f / (float)len : 0.f;
    float acc = 0.f;
    #pragma unroll
    for (int i = 0; i < 8; i++) acc += vsum[i][tid];
    acc *= inv;

    // q_star = [0 | mean]  (h0 slice of X0 not written: iter-0 gemm is K-truncated)
    d_X0[(size_t)g * 768 + tid] = __float2half_rn(0.f);
    d_X0[(size_t)g * 768 + 256 + tid] = __float2half_rn(acc);
}

// ---------------- attention (iters 1..5): fused act1 prologue + online softmax ----
__global__ void attention_kernel(float* __restrict__ dout, int final_iter) {
    int g = blockIdx.x;
    int s = d_starts[g], en = d_starts[g + 1];
    __shared__ float qs[256];
    __shared__ float vsum[8][256];
    __shared__ float wmx[8], wsx[8], wscale[8];
    __shared__ float s_inv;
    int tid = threadIdx.x, lane = tid & 31, w = tid >> 5;

    // ---- fused LSTM layer-1 activation: gates -> (h1, c1); q = h1 ----
    {
        const float* gr = d_gates + (size_t)g * 1024;
        float gi = gr[tid]       + d_b1[tid];
        float gf = gr[tid + 256] + d_b1[tid + 256];
        float gg = gr[tid + 512] + d_b1[tid + 512];
        float go = gr[tid + 768] + d_b1[tid + 768];
        float si = 1.f / (1.f + expf(-gi));
        float sf = 1.f / (1.f + expf(-gf));
        float tg = tanhf(gg);
        float so = 1.f / (1.f + expf(-go));
        size_t ci = (size_t)g * 256 + tid;
        float cn = sf * d_c1[ci] + si * tg;
        d_c1[ci] = cn;
        float hn = so * tanhf(cn);
        qs[tid] = hn;
        d_X1[(size_t)g * 512 + 256 + tid] = __float2half_rn(hn);  // h1 for next gemm1
    }
    __syncthreads();

    float qv[8];
    #pragma unroll
    for (int j = 0; j < 8; j++) qv[j] = qs[8 * lane + j];

    float m = -3.4e38f, ssum = 0.f;
    float v[8];
    #pragma unroll
    for (int j = 0; j < 8; j++) v[j] = 0.f;

    int n = s + w;
    for (; n + 8 < en; n += 16) {
        uint4 p1 = ((const uint4*)(d_nodesh + (size_t)n * 256))[lane];
        uint4 p2 = ((const uint4*)(d_nodesh + (size_t)(n + 8) * 256))[lane];
        float2 a0 = __half22float2(*(__half2*)&p1.x);
        float2 a1 = __half22float2(*(__half2*)&p1.y);
        float2 a2 = __half22float2(*(__half2*)&p1.z);
        float2 a3 = __half22float2(*(__half2*)&p1.w);
        float2 b0 = __half22float2(*(__half2*)&p2.x);
        float2 b1 = __half22float2(*(__half2*)&p2.y);
        float2 b2 = __half22float2(*(__half2*)&p2.z);
        float2 b3 = __half22float2(*(__half2*)&p2.w);
        float x1[8] = {a0.x, a0.y, a1.x, a1.y, a2.x, a2.y, a3.x, a3.y};
        float x2[8] = {b0.x, b0.y, b1.x, b1.y, b2.x, b2.y, b3.x, b3.y};

        float d1 = 0.f, d2 = 0.f;
        #pragma unroll
        for (int j = 0; j < 8; j++) {
            d1 = fmaf(x1[j], qv[j], d1);
            d2 = fmaf(x2[j], qv[j], d2);
        }
        #pragma unroll
        for (int o = 16; o; o >>= 1) {
            d1 += __shfl_xor_sync(0xffffffffu, d1, o);
            d2 += __shfl_xor_sync(0xffffffffu, d2, o);
        }

        float mn = fmaxf(m, fmaxf(d1, d2));
        float scale = __expf(m - mn);
        float e1 = __expf(d1 - mn);
        float e2 = __expf(d2 - mn);
        ssum = ssum * scale + e1 + e2;
        #pragma unroll
        for (int j = 0; j < 8; j++)
            v[j] = fmaf(fmaf(v[j], scale, e1 * x1[j]), 1.f, e2 * x2[j]);
        m = mn;
    }
    for (; n < en; n += 8) {
        uint4 p1 = ((const uint4*)(d_nodesh + (size_t)n * 256))[lane];
        float2 a0 = __half22float2(*(__half2*)&p1.x);
        float2 a1 = __half22float2(*(__half2*)&p1.y);
        float2 a2 = __half22float2(*(__half2*)&p1.z);
        float2 a3 = __half22float2(*(__half2*)&p1.w);
        float x1[8] = {a0.x, a0.y, a1.x, a1.y, a2.x, a2.y, a3.x, a3.y};
        float d1 = 0.f;
        #pragma unroll
        for (int j = 0; j < 8; j++) d1 = fmaf(x1[j], qv[j], d1);
        #pragma unroll
        for (int o = 16; o; o >>= 1) d1 += __shfl_xor_sync(0xffffffffu, d1, o);
        float mn = fmaxf(m, d1);
        float scale = __expf(m - mn);
        float e1 = __expf(d1 - mn);
        ssum = ssum * scale + e1;
        #pragma unroll
        for (int j = 0; j < 8; j++) v[j] = fmaf(v[j], scale, e1 * x1[j]);
        m = mn;
    }

    if (lane == 0) { wmx[w] = m; wsx[w] = ssum; }
    {
        float4* dst = (float4*)&vsum[w][8 * lane];
        dst[0] = make_float4(v[0], v[1], v[2], v[3]);
        dst[1] = make_float4(v[4], v[5], v[6], v[7]);
    }
    __syncthreads();

    if (tid == 0) {
        float M = -3.4e38f;
        #pragma unroll
        for (int i = 0; i < 8; i++) if (wsx[i] > 0.f) M = fmaxf(M, wmx[i]);
        float S = 0.f;
        #pragma unroll
        for (int i = 0; i < 8; i++) {
            float sc = (wsx[i] > 0.f) ? __expf(wmx[i] - M) : 0.f;
            wscale[i] = sc;
            S += wsx[i] * sc;
        }
        s_inv = (S > 0.f) ? 1.f / S : 0.f;
    }
    __syncthreads();

    float acc = 0.f;
    #pragma unroll
    for (int i = 0; i < 8; i++) acc = fmaf(vsum[i][tid], wscale[i], acc);
    acc *= s_inv;

    if (final_iter) {
        dout[(size_t)g * 512 + tid] = qs[tid];
        dout[(size_t)g * 512 + 256 + tid] = acc;
    } else {
        d_X0[(size_t)g * 768 + tid] = __float2half_rn(qs[tid]);
        d_X0[(size_t)g * 768 + 256 + tid] = __float2half_rn(acc);
    }
}

// ---------------- mma.sync fp16 GEMM: gates[:, tn-tile] = X[:, ks:ks+kl] * W^T ----
// CTA tile 128x128, 8 warps (4m x 2n), warp tile 32x64, BK=64,
// 3-stage cp.async, one sync per 64-K iter. K-window [k_start, k_start+k_len).
#define ROWB 144                   // 64 halves (128 B) + 16 B pad; stride 36 words -> conflict-free
#define ARR  (128 * ROWB)          // 18432 B per array
#define STG  (2 * ARR)             // 36864 B per stage (A, B)
#define SMEM_GEMM (3 * STG)        // 110592 B

__global__ __launch_bounds__(256, 1) void mma_gates(int layer, int B, int k_start, int k_len) {
    const __half* __restrict__ Ag = layer ? d_X1 : d_X0;
    const __half* __restrict__ Wg = layer ? d_W1 : d_W0;
    const int Kf = layer ? 512 : 768;

    extern __shared__ __half sm[];
    const uint32_t sbase = smem_u32(sm);

    const int tid = threadIdx.x, lane = tid & 31, warp = tid >> 5;
    const int wm = warp >> 1, wn = warp & 1;
    const int tm = blockIdx.y, tn = blockIdx.x;

    float c[2][8][4];
    #pragma unroll
    for (int i = 0; i < 2; i++)
        #pragma unroll
        for (int j = 0; j < 8; j++)
            #pragma unroll
            for (int k = 0; k < 4; k++) c[i][j][k] = 0.f;

    // cp.async mapping: 1024 chunks (128 rows x 8 x 16B) per array, 4 per thread
    int rowj[4], chj[4], arj[4], brj[4];
    #pragma unroll
    for (int j = 0; j < 4; j++) {
        int idx = tid + 256 * j;
        rowj[j] = idx >> 3;
        chj[j]  = idx & 7;
        int ar = tm * 128 + rowj[j]; if (ar >= B) ar = B - 1;
        arj[j] = ar;
        brj[j] = tn * 128 + rowj[j];
    }

    const int niter = k_len >> 6;

    #define ISSUE(I, BUF) do {                                                    \
        int _k0 = k_start + ((I) << 6);                                           \
        _Pragma("unroll")                                                         \
        for (int j = 0; j < 4; j++) {                                             \
            uint32_t _d = sbase + (BUF) * STG + rowj[j] * ROWB + chj[j] * 16;     \
            cp16(_d,       Ag + (size_t)arj[j] * Kf + _k0 + chj[j] * 8);          \
            cp16(_d + ARR, Wg + (size_t)brj[j] * Kf + _k0 + chj[j] * 8);          \
        }                                                                         \
        CP_COMMIT();                                                              \
    } while (0)

    ISSUE(0, 0);
    ISSUE(1, 1);

    const int m0 = wm * 32, n0 = wn * 64;
    const uint32_t a_row = m0 + (lane & 15);
    const uint32_t a_koff = (lane >> 4) * 16;
    const uint32_t b_row = n0 + (lane & 7) + ((lane >> 4) << 3);
    const uint32_t b_koff = ((lane >> 3) & 1) * 16;

    int buf = 0, nbuf = 2;
    for (int i = 0; i < niter; i++) {
        if (i + 1 < niter) CP_WAIT1(); else CP_WAIT0();
        __syncthreads();
        if (i + 2 < niter) ISSUE(i + 2, nbuf);

        uint32_t aA = sbase + buf * STG;
        uint32_t aB = aA + ARR;

        #pragma unroll
        for (int kk = 0; kk < 4; kk++) {
            uint32_t kb = kk * 32;
            uint32_t ah[2][4], bh[4][4];
            ldsm4(ah[0], aA + a_row * ROWB + kb + a_koff);
            ldsm4(ah[1], aA + (a_row + 16) * ROWB + kb + a_koff);
            #pragma unroll
            for (int nb = 0; nb < 4; nb++)
                ldsm4(bh[nb], aB + (b_row + nb * 16) * ROWB + kb + b_koff);
            #pragma unroll
            for (int mi = 0; mi < 2; mi++)
                #pragma unroll
                for (int nb = 0; nb < 4; nb++)
                    #pragma unroll
                    for (int h = 0; h < 2; h++) {
                        int n8 = nb * 2 + h;
                        mma16816(c[mi][n8], ah[mi], &bh[nb][h * 2]);
                    }
        }
        buf = (buf == 2) ? 0 : buf + 1;
        nbuf = (nbuf == 2) ? 0 : nbuf + 1;
    }

    // epilogue: write fp32 gates
    int g = lane >> 2, qt = lane & 3;
    #pragma unroll
    for (int mi = 0; mi < 2; mi++) {
        #pragma unroll
        for (int n8 = 0; n8 < 8; n8++) {
            int row = tm * 128 + m0 + mi * 16 + g;
            int col = tn * 128 + n0 + n8 * 8 + qt * 2;
            if (row < B)
                *(float2*)&d_gates[(size_t)row * 1024 + col] = make_float2(c[mi][n8][0], c[mi][n8][1]);
            if (row + 8 < B)
                *(float2*)&d_gates[(size_t)(row + 8) * 1024 + col] = make_float2(c[mi][n8][2], c[mi][n8][3]);
        }
    }
    #undef ISSUE
}

// ---------------- LSTM layer-0 pointwise: gates -> (h0, c0), writes fp16 inputs ----
__global__ void lstm_act0_kernel(int B) {
    int idx = blockIdx.x * blockDim.x + threadIdx.x;
    if (idx >= B * 256) return;
    int b = idx >> 8, t = idx & 255;
    const float* gr = d_gates + (size_t)b * 1024;

    float gi = gr[t]       + d_b0[t];
    float gf = gr[t + 256] + d_b0[t + 256];
    float gg = gr[t + 512] + d_b0[t + 512];
    float go = gr[t + 768] + d_b0[t + 768];

    float si = 1.f / (1.f + expf(-gi));
    float sf = 1.f / (1.f + expf(-gf));
    float tg = tanhf(gg);
    float so = 1.f / (1.f + expf(-go));

    float cn = sf * d_c0[idx] + si * tg;
    d_c0[idx] = cn;
    float hn = so * tanhf(cn);

    __half h = __float2half_rn(hn);
    d_X0[(size_t)b * 768 + 512 + t] = h;
    d_X1[(size_t)b * 512 + t]       = h;
}

// ---------------- host launcher ----------------
extern "C" void kernel_launch(void* const* d_in, const int* in_sizes, int n_in,
                              void* d_out, int out_size) {
    const float* nodes = (const float*)d_in[0];
    const void*  gid   = d_in[1];
    int N = in_sizes[1];

    int wbase = (in_sizes[2] == 1) ? 3 : 2;
    const float* Wih0 = (const float*)d_in[wbase + 0];
    const float* Whh0 = (const float*)d_in[wbase + 1];
    const float* bih0 = (const float*)d_in[wbase + 2];
    const float* bhh0 = (const float*)d_in[wbase + 3];
    const float* Wih1 = (const float*)d_in[wbase + 4];
    const float* Whh1 = (const float*)d_in[wbase + 5];
    const float* bih1 = (const float*)d_in[wbase + 6];
    const float* bhh1 = (const float*)d_in[wbase + 7];

    int B = out_size / (2 * Hh);
    float* out = (float*)d_out;

    cudaFuncSetAttribute(mma_gates, cudaFuncAttributeMaxDynamicSharedMemorySize, SMEM_GEMM);

    starts_kernel<<<(B + 1 + 255) / 256, 256>>>((const int*)gid, N, B);
    int pack_n = (B * 768 > 1024 * 768) ? B * 768 : 1024 * 768;
    pack_kernel<<<(pack_n + 255) / 256, 256>>>(Wih0, Whh0, bih0, bhh0,
                                               Wih1, Whh1, bih1, bhh1, B);

    dim3 gemm_grid(1024 / 128, (B + 127) / 128);
    const int M_ITERS = 6;
    for (int i = 0; i < M_ITERS; i++) {
        int final_iter = (i == M_ITERS - 1) ? 1 : 0;
        if (i == 0) {
            convert_mean_kernel<<<B, 256>>>(nodes);   // q=0: r = mean, emit fp16 copy
        } else {
            attention_kernel<<<B, 256>>>(out, final_iter);  // fused act1 prologue
        }
        if (!final_iter) {
            if (i == 0) {
                // X0 = [0 | r | 0], X1 = [h0 | 0]: only the nonzero K-slices
                mma_gates<<<gemm_grid, 256, SMEM_GEMM>>>(0, B, 256, 256);
                lstm_act0_kernel<<<(B * 256 + 255) / 256, 256>>>(B);
                mma_gates<<<gemm_grid, 256, SMEM_GEMM>>>(1, B, 0, 256);
            } else {
                mma_gates<<<gemm_grid, 256, SMEM_GEMM>>>(0, B, 0, 768);
                lstm_act0_kernel<<<(B * 256 + 255) / 256, 256>>>(B);
                mma_gates<<<gemm_grid, 256, SMEM_GEMM>>>(1, B, 0, 512);
            }
        }
    }
}